// round 2
// baseline (speedup 1.0000x reference)
#include <cuda_runtime.h>
#include <math.h>

// SequenceAttLayer: B=4096, T=200, H=64; MLP 256->80->40->1, masked softmax, att@keys.
// Algebra: x=[q,k,q-k,q*k];  x.W1 = k.(W1b-W1c + diag(q).W1d) + [q.(W1a+W1c)+b1]
// -> per-b W_eff[64x80] + c[80]; layer1 is a 64-deep dot per (t,j).

#define T_DIM 200
#define H_DIM 64
#define D1 80
#define D2 40

#define KS_STRIDE 68   // 64 + 4 pad
#define H1_STRIDE 81   // 80 + 1 pad

// shared layout (floats)
#define OFF_WEFF   0                    // 64*80 = 5120
#define OFF_C      (OFF_WEFF + 5120)    // 80
#define OFF_W2     (OFF_C + 80)         // 80*40 = 3200
#define OFF_B2     (OFF_W2 + 3200)      // 40
#define OFF_WD     (OFF_B2 + 40)        // 40
#define OFF_Q      (OFF_WD + 40)        // 64
#define OFF_KS     (OFF_Q + 64)         // 64*68 = 4352
#define OFF_H1     (OFF_KS + 4352)      // 64*81 = 5184
#define OFF_SC     (OFF_H1 + 5184)      // 200
#define OFF_RED    (OFF_SC + 200)       // 8
#define OFF_RED2   (OFF_RED + 8)        // 8
#define OFF_OBUF   (OFF_RED2 + 8)       // 256
#define SMEM_FLOATS (OFF_OBUF + 256)

__global__ __launch_bounds__(256, 2)
void seqatt_kernel(const float* __restrict__ queries,
                   const float* __restrict__ keys,
                   const int* __restrict__ keys_length,
                   const float* __restrict__ W1,
                   const float* __restrict__ b1,
                   const float* __restrict__ W2,
                   const float* __restrict__ b2,
                   const float* __restrict__ Wd,
                   float* __restrict__ out)
{
    extern __shared__ float sm[];
    float* W_eff = sm + OFF_WEFF;
    float* c_s   = sm + OFF_C;
    float* W2_s  = sm + OFF_W2;
    float* b2_s  = sm + OFF_B2;
    float* Wd_s  = sm + OFF_WD;
    float* q_s   = sm + OFF_Q;
    float* K_s   = sm + OFF_KS;
    float* H1    = sm + OFF_H1;
    float* sc    = sm + OFF_SC;
    float* red   = sm + OFF_RED;
    float* red2  = sm + OFF_RED2;
    float* obuf  = sm + OFF_OBUF;

    const int b   = blockIdx.x;
    const int tid = threadIdx.x;
    // keys_length is int32 on device (JAX x64 disabled downcasts int64->int32).
    int len = keys_length[b];
    len = len < 1 ? 1 : (len > T_DIM ? T_DIM : len);   // defensive clamp, semantics-neutral

    // ---- phase 0: stage weights / q, build W_eff and c ----
    if (tid < H_DIM) q_s[tid] = queries[b * H_DIM + tid];
    for (int i = tid; i < D1 * D2; i += 256) W2_s[i] = W2[i];
    if (tid < D2) { b2_s[tid] = b2[tid]; Wd_s[tid] = Wd[tid]; }
    __syncthreads();

    for (int i = tid; i < H_DIM * D1; i += 256) {
        int h = i / D1;
        int j = i - h * D1;
        float wb = W1[(64 + h) * D1 + j];
        float wc = W1[(128 + h) * D1 + j];
        float wd = W1[(192 + h) * D1 + j];
        W_eff[i] = wb - wc + q_s[h] * wd;
    }
    if (tid < D1) {
        float acc = b1[tid];
        #pragma unroll 8
        for (int h = 0; h < H_DIM; h++)
            acc += q_s[h] * (W1[h * D1 + tid] + W1[(128 + h) * D1 + tid]);
        c_s[tid] = acc;
    }
    __syncthreads();

    // thread tilings
    const int ty  = tid >> 4;          // 0..15 : 4 rows each (layer1)
    const int tx  = tid & 15;          // 0..15 : cols {tx, tx+16, .., tx+64}
    const int ty2 = tid >> 3;          // 0..31 : 2 rows each (layer2)
    const int tx2 = tid & 7;           // 0..7  : cols {tx2, tx2+8, .., tx2+32}
    const int ty4 = ty << 2;
    const int t2r = ty2 << 1;

    const int nchunk = (len + 63) >> 6;

    for (int ch = 0; ch < nchunk; ch++) {
        const int t0 = ch << 6;

        // stage 64 key rows (zero-pad past T)
        for (int i = tid; i < 64 * 64; i += 256) {
            int t = i >> 6, h = i & 63;
            int tg = t0 + t;
            K_s[t * KS_STRIDE + h] =
                (tg < T_DIM) ? keys[(b * T_DIM + tg) * H_DIM + h] : 0.f;
        }
        __syncthreads();

        // ---- layer 1: z[64x80] = K_s[64x64] @ W_eff[64x80] + c ----
        float acc[4][5];
        #pragma unroll
        for (int r = 0; r < 4; r++)
            #pragma unroll
            for (int cc = 0; cc < 5; cc++) acc[r][cc] = 0.f;

        const float* Wp = W_eff + tx;
        const float* K0 = K_s + ty4 * KS_STRIDE;
        #pragma unroll 8
        for (int kk = 0; kk < 64; kk++) {
            float a0 = K0[kk];
            float a1 = K0[KS_STRIDE + kk];
            float a2 = K0[2 * KS_STRIDE + kk];
            float a3 = K0[3 * KS_STRIDE + kk];
            float w0 = Wp[kk * D1];
            float w1 = Wp[kk * D1 + 16];
            float w2 = Wp[kk * D1 + 32];
            float w3 = Wp[kk * D1 + 48];
            float w4 = Wp[kk * D1 + 64];
            acc[0][0] += a0 * w0; acc[0][1] += a0 * w1; acc[0][2] += a0 * w2; acc[0][3] += a0 * w3; acc[0][4] += a0 * w4;
            acc[1][0] += a1 * w0; acc[1][1] += a1 * w1; acc[1][2] += a1 * w2; acc[1][3] += a1 * w3; acc[1][4] += a1 * w4;
            acc[2][0] += a2 * w0; acc[2][1] += a2 * w1; acc[2][2] += a2 * w2; acc[2][3] += a2 * w3; acc[2][4] += a2 * w4;
            acc[3][0] += a3 * w0; acc[3][1] += a3 * w1; acc[3][2] += a3 * w2; acc[3][3] += a3 * w3; acc[3][4] += a3 * w4;
        }
        #pragma unroll
        for (int r = 0; r < 4; r++) {
            #pragma unroll
            for (int cc = 0; cc < 5; cc++) {
                int j = tx + 16 * cc;
                float z = acc[r][cc] + c_s[j];
                H1[(ty4 + r) * H1_STRIDE + j] = 1.f / (1.f + __expf(-z));
            }
        }
        __syncthreads();

        // ---- layer 2 + head: h2 = sig(H1@W2 + b2); score = h2 . Wd ----
        float acc2[2][5];
        #pragma unroll
        for (int r = 0; r < 2; r++)
            #pragma unroll
            for (int cc = 0; cc < 5; cc++) acc2[r][cc] = 0.f;

        const float* Hp = H1 + t2r * H1_STRIDE;
        const float* W2p = W2_s + tx2;
        #pragma unroll 8
        for (int kk = 0; kk < D1; kk++) {
            float a0 = Hp[kk];
            float a1 = Hp[H1_STRIDE + kk];
            float w0 = W2p[kk * D2];
            float w1 = W2p[kk * D2 + 8];
            float w2 = W2p[kk * D2 + 16];
            float w3 = W2p[kk * D2 + 24];
            float w4 = W2p[kk * D2 + 32];
            acc2[0][0] += a0 * w0; acc2[0][1] += a0 * w1; acc2[0][2] += a0 * w2; acc2[0][3] += a0 * w3; acc2[0][4] += a0 * w4;
            acc2[1][0] += a1 * w0; acc2[1][1] += a1 * w1; acc2[1][2] += a1 * w2; acc2[1][3] += a1 * w3; acc2[1][4] += a1 * w4;
        }
        float ps0 = 0.f, ps1 = 0.f;
        #pragma unroll
        for (int cc = 0; cc < 5; cc++) {
            int j2 = tx2 + 8 * cc;
            float bb = b2_s[j2], ww = Wd_s[j2];
            float h20 = 1.f / (1.f + __expf(-(acc2[0][cc] + bb)));
            float h21 = 1.f / (1.f + __expf(-(acc2[1][cc] + bb)));
            ps0 += h20 * ww;
            ps1 += h21 * ww;
        }
        // reduce over tx2 (low 3 lane bits)
        #pragma unroll
        for (int m = 1; m < 8; m <<= 1) {
            ps0 += __shfl_xor_sync(0xffffffffu, ps0, m);
            ps1 += __shfl_xor_sync(0xffffffffu, ps1, m);
        }
        if (tx2 == 0) {
            int tg = t0 + t2r;
            if (tg < T_DIM)     sc[tg]     = ps0;
            if (tg + 1 < T_DIM) sc[tg + 1] = ps1;
        }
        __syncthreads();
    }

    // ---- softmax over valid positions (scale 1/sqrt(64), bd cancels) ----
    float v = -INFINITY;
    if (tid < len) v = sc[tid] * 0.125f;
    float m = v;
    #pragma unroll
    for (int s = 16; s; s >>= 1) m = fmaxf(m, __shfl_xor_sync(0xffffffffu, m, s));
    if ((tid & 31) == 0) red[tid >> 5] = m;
    __syncthreads();
    if (tid == 0) {
        float mm = red[0];
        #pragma unroll
        for (int i = 1; i < 8; i++) mm = fmaxf(mm, red[i]);
        red[0] = mm;
    }
    __syncthreads();
    const float M = red[0];

    float e = (tid < len) ? __expf(v - M) : 0.f;
    float s = e;
    #pragma unroll
    for (int w = 16; w; w >>= 1) s += __shfl_xor_sync(0xffffffffu, s, w);
    if ((tid & 31) == 0) red2[tid >> 5] = s;
    __syncthreads();
    if (tid == 0) {
        float ss = red2[0];
        #pragma unroll
        for (int i = 1; i < 8; i++) ss += red2[i];
        red2[0] = ss;
    }
    __syncthreads();
    const float inv_sum = 1.f / red2[0];
    if (tid < T_DIM) sc[tid] = e * inv_sum;
    __syncthreads();

    // ---- out[h] = sum_t att[t] * keys[b,t,h] ----
    {
        const int g  = tid >> 6;   // 0..3
        const int hh = tid & 63;
        float acc = 0.f;
        for (int t = g; t < len; t += 4)
            acc += sc[t] * keys[(b * T_DIM + t) * H_DIM + hh];
        obuf[tid] = acc;
        __syncthreads();
        if (tid < H_DIM)
            out[b * H_DIM + tid] =
                obuf[tid] + obuf[64 + tid] + obuf[128 + tid] + obuf[192 + tid];
    }
}

extern "C" void kernel_launch(void* const* d_in, const int* in_sizes, int n_in,
                              void* d_out, int out_size)
{
    const float* queries = (const float*)d_in[0];
    const float* keys    = (const float*)d_in[1];
    const int*   klen    = (const int*)d_in[2];
    const float* W1      = (const float*)d_in[3];
    const float* b1      = (const float*)d_in[4];
    const float* W2      = (const float*)d_in[5];
    const float* b2      = (const float*)d_in[6];
    const float* Wd      = (const float*)d_in[7];
    // d_in[8] = bd : uniform shift, cancels in softmax
    float* out = (float*)d_out;

    const int B = in_sizes[2];  // keys_length count
    const size_t smem = SMEM_FLOATS * sizeof(float);
    cudaFuncSetAttribute(seqatt_kernel,
                         cudaFuncAttributeMaxDynamicSharedMemorySize, (int)smem);
    seqatt_kernel<<<B, 256, smem>>>(queries, keys, klen, W1, b1, W2, b2, Wd, out);
}

// round 3
// speedup vs baseline: 1.0518x; 1.0518x over previous
#include <cuda_runtime.h>
#include <math.h>

// SequenceAttLayer: B=4096, T=200, H=64; MLP 256->80->40->1, masked softmax, att@keys.
// Algebra: x=[q,k,q-k,q*k];  x.W1 = k.(W1b-W1c + diag(q).W1d) + [q.(W1a+W1c)+b1]
// -> per-b W_eff[64x80] + c[80]; layer1 is a 64-deep dot per (t,j).
// This version: k-paired packed fp32 math (fma.rn.f32x2) with transposed weight
// tiles so both operands load pre-packed via LDS.128 (no pack instructions).

#define T_DIM 200
#define H_DIM 64
#define D1 80
#define D2 40

#define KS_STRIDE  68   // K_s   [t][h],  h contiguous (k-dim of layer1)
#define WT_STRIDE  68   // W_t   [j][h],  h contiguous (transposed W_eff)
#define H1_STRIDE  84   // H1    [t][j],  j contiguous (k-dim of layer2), mult of 4
#define W2T_STRIDE 84   // W2_t  [n][j],  j contiguous (transposed W2)

// shared layout (floats)
#define OFF_WT     0                     // 80*68 = 5440
#define OFF_C      (OFF_WT + 5440)       // 80
#define OFF_W2T    (OFF_C + 80)          // 40*84 = 3360
#define OFF_B2     (OFF_W2T + 3360)      // 40
#define OFF_WD     (OFF_B2 + 40)         // 40
#define OFF_Q      (OFF_WD + 40)         // 64
#define OFF_KS     (OFF_Q + 64)          // 64*68 = 4352
#define OFF_H1     (OFF_KS + 4352)       // 64*84 = 5376
#define OFF_SC     (OFF_H1 + 5376)       // 200
#define OFF_RED    (OFF_SC + 200)        // 8
#define OFF_RED2   (OFF_RED + 8)         // 8
#define OFF_OBUF   (OFF_RED2 + 8)        // 256
#define SMEM_FLOATS (OFF_OBUF + 256)     // 19224 floats = 76896 B

typedef unsigned long long ull;

__device__ __forceinline__ ull ffma2(ull a, ull b, ull c) {
    ull d;
    asm("fma.rn.f32x2 %0, %1, %2, %3;" : "=l"(d) : "l"(a), "l"(b), "l"(c));
    return d;
}
__device__ __forceinline__ float pair_sum(ull v) {
    float2 f = *reinterpret_cast<float2*>(&v);
    return f.x + f.y;
}

__global__ __launch_bounds__(256, 2)
void seqatt_kernel(const float* __restrict__ queries,
                   const float* __restrict__ keys,
                   const int* __restrict__ keys_length,
                   const float* __restrict__ W1,
                   const float* __restrict__ b1,
                   const float* __restrict__ W2,
                   const float* __restrict__ b2,
                   const float* __restrict__ Wd,
                   float* __restrict__ out)
{
    extern __shared__ float sm[];
    float* W_t   = sm + OFF_WT;
    float* c_s   = sm + OFF_C;
    float* W2_t  = sm + OFF_W2T;
    float* b2_s  = sm + OFF_B2;
    float* Wd_s  = sm + OFF_WD;
    float* q_s   = sm + OFF_Q;
    float* K_s   = sm + OFF_KS;
    float* H1    = sm + OFF_H1;
    float* sc    = sm + OFF_SC;
    float* red   = sm + OFF_RED;
    float* red2  = sm + OFF_RED2;
    float* obuf  = sm + OFF_OBUF;

    const int b   = blockIdx.x;
    const int tid = threadIdx.x;
    // keys_length is int32 on device (JAX x64-disabled downcasts int64->int32).
    int len = keys_length[b];
    len = len < 1 ? 1 : (len > T_DIM ? T_DIM : len);

    // ---- phase 0: stage q, transposed weights; build W_t and c ----
    if (tid < H_DIM) q_s[tid] = queries[b * H_DIM + tid];
    if (tid < D2) { b2_s[tid] = b2[tid]; Wd_s[tid] = Wd[tid]; }
    // W2_t[n][j] = W2[j][n]  (coalesced reads of W2)
    for (int i = tid; i < D1 * D2; i += 256) {
        int j = i / D2, n = i - j * D2;
        W2_t[n * W2T_STRIDE + j] = W2[i];
    }
    __syncthreads();

    // W_t[j][h] = W1b[h][j] - W1c[h][j] + q[h]*W1d[h][j]  (coalesced W1 reads)
    for (int i = tid; i < H_DIM * D1; i += 256) {
        int h = i / D1, j = i - h * D1;
        float wb = W1[(64  + h) * D1 + j];
        float wc = W1[(128 + h) * D1 + j];
        float wd = W1[(192 + h) * D1 + j];
        W_t[j * WT_STRIDE + h] = wb - wc + q_s[h] * wd;
    }
    if (tid < D1) {
        float acc = b1[tid];
        #pragma unroll 8
        for (int h = 0; h < H_DIM; h++)
            acc += q_s[h] * (W1[h * D1 + tid] + W1[(128 + h) * D1 + tid]);
        c_s[tid] = acc;
    }
    __syncthreads();

    // thread tilings
    const int ty  = tid >> 4;       // 0..15 : layer1, 4 rows each (rows 4ty..4ty+3)
    const int tx  = tid & 15;       // 0..15 : layer1 cols {tx + 16m}, m=0..4
    const int ty2 = tid >> 3;       // 0..31 : layer2, 2 rows each (rows 2ty2, 2ty2+1)
    const int tx2 = tid & 7;        // 0..7  : layer2 cols {tx2 + 8m}, m=0..4
    const int ty4 = ty << 2;
    const int t2r = ty2 << 1;

    const int nchunk = (len + 63) >> 6;

    for (int ch = 0; ch < nchunk; ch++) {
        const int t0 = ch << 6;

        // stage 64 key rows (zero-pad past T)
        for (int i = tid; i < 64 * 64; i += 256) {
            int t = i >> 6, h = i & 63;
            int tg = t0 + t;
            K_s[t * KS_STRIDE + h] =
                (tg < T_DIM) ? keys[(b * T_DIM + tg) * H_DIM + h] : 0.f;
        }
        __syncthreads();

        // ---- layer 1: z[64x80] = K_s[64x64] @ W_eff + c, packed over k ----
        ull acc1[4][5];
        #pragma unroll
        for (int r = 0; r < 4; r++)
            #pragma unroll
            for (int m = 0; m < 5; m++) acc1[r][m] = 0ull;

        const float* K0 = K_s + ty4 * KS_STRIDE;
        const float* Wt0 = W_t + tx * WT_STRIDE;
        #pragma unroll 4
        for (int k4 = 0; k4 < 64; k4 += 4) {
            ulonglong2 a[4], w[5];
            #pragma unroll
            for (int r = 0; r < 4; r++)
                a[r] = *reinterpret_cast<const ulonglong2*>(K0 + r * KS_STRIDE + k4);
            #pragma unroll
            for (int m = 0; m < 5; m++)
                w[m] = *reinterpret_cast<const ulonglong2*>(Wt0 + (16 * m) * WT_STRIDE + k4);
            #pragma unroll
            for (int r = 0; r < 4; r++) {
                #pragma unroll
                for (int m = 0; m < 5; m++) {
                    acc1[r][m] = ffma2(a[r].x, w[m].x, acc1[r][m]);
                    acc1[r][m] = ffma2(a[r].y, w[m].y, acc1[r][m]);
                }
            }
        }
        #pragma unroll
        for (int r = 0; r < 4; r++) {
            #pragma unroll
            for (int m = 0; m < 5; m++) {
                int j = tx + 16 * m;
                float z = pair_sum(acc1[r][m]) + c_s[j];
                H1[(ty4 + r) * H1_STRIDE + j] = 1.f / (1.f + __expf(-z));
            }
        }
        __syncthreads();

        // ---- layer 2 + head: h2 = sig(H1@W2 + b2); score = h2 . Wd ----
        ull acc2[2][5];
        #pragma unroll
        for (int r = 0; r < 2; r++)
            #pragma unroll
            for (int m = 0; m < 5; m++) acc2[r][m] = 0ull;

        const float* Hp  = H1 + t2r * H1_STRIDE;
        const float* W20 = W2_t + tx2 * W2T_STRIDE;
        #pragma unroll 4
        for (int j4 = 0; j4 < D1; j4 += 4) {
            ulonglong2 a0 = *reinterpret_cast<const ulonglong2*>(Hp + j4);
            ulonglong2 a1 = *reinterpret_cast<const ulonglong2*>(Hp + H1_STRIDE + j4);
            ulonglong2 w[5];
            #pragma unroll
            for (int m = 0; m < 5; m++)
                w[m] = *reinterpret_cast<const ulonglong2*>(W20 + (8 * m) * W2T_STRIDE + j4);
            #pragma unroll
            for (int m = 0; m < 5; m++) {
                acc2[0][m] = ffma2(a0.x, w[m].x, acc2[0][m]);
                acc2[0][m] = ffma2(a0.y, w[m].y, acc2[0][m]);
                acc2[1][m] = ffma2(a1.x, w[m].x, acc2[1][m]);
                acc2[1][m] = ffma2(a1.y, w[m].y, acc2[1][m]);
            }
        }
        float ps0 = 0.f, ps1 = 0.f;
        #pragma unroll
        for (int m = 0; m < 5; m++) {
            int n = tx2 + 8 * m;
            float bb = b2_s[n], ww = Wd_s[n];
            float h20 = 1.f / (1.f + __expf(-(pair_sum(acc2[0][m]) + bb)));
            float h21 = 1.f / (1.f + __expf(-(pair_sum(acc2[1][m]) + bb)));
            ps0 += h20 * ww;
            ps1 += h21 * ww;
        }
        #pragma unroll
        for (int m = 1; m < 8; m <<= 1) {
            ps0 += __shfl_xor_sync(0xffffffffu, ps0, m);
            ps1 += __shfl_xor_sync(0xffffffffu, ps1, m);
        }
        if (tx2 == 0) {
            int tg = t0 + t2r;
            if (tg < T_DIM)     sc[tg]     = ps0;
            if (tg + 1 < T_DIM) sc[tg + 1] = ps1;
        }
        __syncthreads();
    }

    // ---- softmax over valid positions (scale 1/sqrt(64), bd cancels) ----
    float v = -INFINITY;
    if (tid < len) v = sc[tid] * 0.125f;
    float m = v;
    #pragma unroll
    for (int s = 16; s; s >>= 1) m = fmaxf(m, __shfl_xor_sync(0xffffffffu, m, s));
    if ((tid & 31) == 0) red[tid >> 5] = m;
    __syncthreads();
    if (tid == 0) {
        float mm = red[0];
        #pragma unroll
        for (int i = 1; i < 8; i++) mm = fmaxf(mm, red[i]);
        red[0] = mm;
    }
    __syncthreads();
    const float M = red[0];

    float e = (tid < len) ? __expf(v - M) : 0.f;
    float s = e;
    #pragma unroll
    for (int w = 16; w; w >>= 1) s += __shfl_xor_sync(0xffffffffu, s, w);
    if ((tid & 31) == 0) red2[tid >> 5] = s;
    __syncthreads();
    if (tid == 0) {
        float ss = red2[0];
        #pragma unroll
        for (int i = 1; i < 8; i++) ss += red2[i];
        red2[0] = ss;
    }
    __syncthreads();
    const float inv_sum = 1.f / red2[0];
    if (tid < T_DIM) sc[tid] = e * inv_sum;
    __syncthreads();

    // ---- out[h] = sum_t att[t] * keys[b,t,h] ----
    {
        const int g  = tid >> 6;   // 0..3
        const int hh = tid & 63;
        float acc = 0.f;
        for (int t = g; t < len; t += 4)
            acc += sc[t] * keys[(b * T_DIM + t) * H_DIM + hh];
        obuf[tid] = acc;
        __syncthreads();
        if (tid < H_DIM)
            out[b * H_DIM + tid] =
                obuf[tid] + obuf[64 + tid] + obuf[128 + tid] + obuf[192 + tid];
    }
}

extern "C" void kernel_launch(void* const* d_in, const int* in_sizes, int n_in,
                              void* d_out, int out_size)
{
    const float* queries = (const float*)d_in[0];
    const float* keys    = (const float*)d_in[1];
    const int*   klen    = (const int*)d_in[2];
    const float* W1      = (const float*)d_in[3];
    const float* b1      = (const float*)d_in[4];
    const float* W2      = (const float*)d_in[5];
    const float* b2      = (const float*)d_in[6];
    const float* Wd      = (const float*)d_in[7];
    // d_in[8] = bd : uniform shift, cancels in softmax
    float* out = (float*)d_out;

    const int B = in_sizes[2];  // keys_length count
    const size_t smem = SMEM_FLOATS * sizeof(float);
    cudaFuncSetAttribute(seqatt_kernel,
                         cudaFuncAttributeMaxDynamicSharedMemorySize, (int)smem);
    seqatt_kernel<<<B, 256, smem>>>(queries, keys, klen, W1, b1, W2, b2, Wd, out);
}

// round 4
// speedup vs baseline: 1.2540x; 1.1923x over previous
#include <cuda_runtime.h>
#include <math.h>

// SequenceAttLayer: B=4096, T=200, H=64; MLP 256->80->40->1, masked softmax, att@keys.
// Algebra: x=[q,k,q-k,q*k];  x.W1 = k.(W1b-W1c + diag(q).W1d) + [q.(W1a+W1c)+b1]
// Round 4: no K smem staging (direct LDG broadcast), 3 CTAs/SM (regs<=84,
// smem 58.8KB), conflict-free W_t stride 66, 2 barriers/chunk, f32x2 math.

#define T_DIM 200
#define H_DIM 64
#define D1 80
#define D2 40

#define WT_STRIDE  66   // W_t  [j][h], h contiguous; 2*tx banks -> conflict-free LDS.64
#define H1_STRIDE  84   // H1   [t][j], j contiguous, 16B-aligned rows
#define W2T_STRIDE 84   // W2_t [n][j], j contiguous

// shared layout (floats)
#define OFF_WT     0                     // 80*66 = 5280
#define OFF_C      5280                  // 80
#define OFF_W2T    5360                  // 40*84 = 3360
#define OFF_B2     8720                  // 40
#define OFF_WD     8760                  // 40
#define OFF_Q      8800                  // 64
#define OFF_H1     8864                  // 64*84 = 5376
#define OFF_SC     14240                 // 200
#define OFF_RED    14440                 // 8
#define OFF_RED2   14448                 // 8
#define OFF_OBUF   14456                 // 256
#define SMEM_FLOATS 14712                // 58848 B -> 3 CTAs/SM

typedef unsigned long long ull;

__device__ __forceinline__ ull ffma2(ull a, ull b, ull c) {
    ull d;
    asm("fma.rn.f32x2 %0, %1, %2, %3;" : "=l"(d) : "l"(a), "l"(b), "l"(c));
    return d;
}
__device__ __forceinline__ float pair_sum(ull v) {
    float2 f = *reinterpret_cast<float2*>(&v);
    return f.x + f.y;
}

__global__ __launch_bounds__(256, 3)
void seqatt_kernel(const float* __restrict__ queries,
                   const float* __restrict__ keys,
                   const int* __restrict__ keys_length,
                   const float* __restrict__ W1,
                   const float* __restrict__ b1,
                   const float* __restrict__ W2,
                   const float* __restrict__ b2,
                   const float* __restrict__ Wd,
                   float* __restrict__ out)
{
    extern __shared__ float sm[];
    float* W_t   = sm + OFF_WT;
    float* c_s   = sm + OFF_C;
    float* W2_t  = sm + OFF_W2T;
    float* b2_s  = sm + OFF_B2;
    float* Wd_s  = sm + OFF_WD;
    float* q_s   = sm + OFF_Q;
    float* H1    = sm + OFF_H1;
    float* sc    = sm + OFF_SC;
    float* red   = sm + OFF_RED;
    float* red2  = sm + OFF_RED2;
    float* obuf  = sm + OFF_OBUF;

    const int b   = blockIdx.x;
    const int tid = threadIdx.x;
    // keys_length is int32 on device (JAX x64-disabled downcasts int64->int32).
    int len = keys_length[b];
    len = len < 1 ? 1 : (len > T_DIM ? T_DIM : len);

    // ---- phase 0: stage q, transposed weights; build W_t and c ----
    if (tid < H_DIM) q_s[tid] = queries[b * H_DIM + tid];
    if (tid < D2) { b2_s[tid] = b2[tid]; Wd_s[tid] = Wd[tid]; }
    for (int i = tid; i < D1 * D2; i += 256) {      // W2_t[n][j] = W2[j][n]
        int j = i / D2, n = i - j * D2;
        W2_t[n * W2T_STRIDE + j] = W2[i];
    }
    __syncthreads();

    // W_t[j][h] = W1b[h][j] - W1c[h][j] + q[h]*W1d[h][j]
    for (int i = tid; i < H_DIM * D1; i += 256) {
        int h = i / D1, j = i - h * D1;
        float wb = W1[(64  + h) * D1 + j];
        float wc = W1[(128 + h) * D1 + j];
        float wd = W1[(192 + h) * D1 + j];
        W_t[j * WT_STRIDE + h] = wb - wc + q_s[h] * wd;
    }
    if (tid < D1) {
        float acc = b1[tid];
        #pragma unroll 8
        for (int h = 0; h < H_DIM; h++)
            acc += q_s[h] * (W1[h * D1 + tid] + W1[(128 + h) * D1 + tid]);
        c_s[tid] = acc;
    }

    // thread tilings
    const int ty  = tid >> 4;       // layer1: rows 4ty..4ty+3
    const int tx  = tid & 15;       // layer1: cols {tx + 16m}
    const int ty2 = tid >> 3;       // layer2: rows 2ty2, 2ty2+1
    const int tx2 = tid & 7;        // layer2: cols {tx2 + 8m}
    const int ty4 = ty << 2;
    const int t2r = ty2 << 1;

    const float* Wt0 = W_t + tx * WT_STRIDE;
    const float* Kbase = keys + (size_t)b * T_DIM * H_DIM;

    const int nchunk = (len + 63) >> 6;

    for (int ch = 0; ch < nchunk; ch++) {
        const int t0 = ch << 6;
        __syncthreads();   // W_t/c ready (ch 0); prev layer2 done reading H1 (ch>0)

        // ---- layer 1: z[64x80] = K[64x64] @ W_eff + c, packed over k ----
        // K rows read straight from gmem: all 16 tx lanes share the address
        // (L1 broadcast); row index clamped so the tail chunk stays in-bounds
        // (garbage rows only feed softmax-masked positions).
        const float* Ka0;
        const float* Ka1;
        const float* Ka2;
        const float* Ka3;
        {
            int r0 = t0 + ty4;
            int r1 = r0 + 1, r2 = r0 + 2, r3 = r0 + 3;
            r0 = r0 < T_DIM ? r0 : T_DIM - 1;
            r1 = r1 < T_DIM ? r1 : T_DIM - 1;
            r2 = r2 < T_DIM ? r2 : T_DIM - 1;
            r3 = r3 < T_DIM ? r3 : T_DIM - 1;
            Ka0 = Kbase + r0 * H_DIM; Ka1 = Kbase + r1 * H_DIM;
            Ka2 = Kbase + r2 * H_DIM; Ka3 = Kbase + r3 * H_DIM;
        }

        ull acc1[4][5];
        #pragma unroll
        for (int r = 0; r < 4; r++)
            #pragma unroll
            for (int m = 0; m < 5; m++) acc1[r][m] = 0ull;

        #pragma unroll 2
        for (int k4 = 0; k4 < 64; k4 += 4) {
            ulonglong2 a0 = *reinterpret_cast<const ulonglong2*>(Ka0 + k4);
            ulonglong2 a1 = *reinterpret_cast<const ulonglong2*>(Ka1 + k4);
            ulonglong2 a2 = *reinterpret_cast<const ulonglong2*>(Ka2 + k4);
            ulonglong2 a3 = *reinterpret_cast<const ulonglong2*>(Ka3 + k4);
            #pragma unroll
            for (int m = 0; m < 5; m++) {
                ull w = *reinterpret_cast<const ull*>(Wt0 + (16 * m) * WT_STRIDE + k4);
                acc1[0][m] = ffma2(a0.x, w, acc1[0][m]);
                acc1[1][m] = ffma2(a1.x, w, acc1[1][m]);
                acc1[2][m] = ffma2(a2.x, w, acc1[2][m]);
                acc1[3][m] = ffma2(a3.x, w, acc1[3][m]);
            }
            #pragma unroll
            for (int m = 0; m < 5; m++) {
                ull w = *reinterpret_cast<const ull*>(Wt0 + (16 * m) * WT_STRIDE + k4 + 2);
                acc1[0][m] = ffma2(a0.y, w, acc1[0][m]);
                acc1[1][m] = ffma2(a1.y, w, acc1[1][m]);
                acc1[2][m] = ffma2(a2.y, w, acc1[2][m]);
                acc1[3][m] = ffma2(a3.y, w, acc1[3][m]);
            }
        }
        #pragma unroll
        for (int r = 0; r < 4; r++) {
            #pragma unroll
            for (int m = 0; m < 5; m++) {
                int j = tx + 16 * m;
                float z = pair_sum(acc1[r][m]) + c_s[j];
                H1[(ty4 + r) * H1_STRIDE + j] = 1.f / (1.f + __expf(-z));
            }
        }
        __syncthreads();

        // ---- layer 2 + head: h2 = sig(H1@W2 + b2); score = h2 . Wd ----
        ull acc2[2][5];
        #pragma unroll
        for (int r = 0; r < 2; r++)
            #pragma unroll
            for (int m = 0; m < 5; m++) acc2[r][m] = 0ull;

        const float* Hp  = H1 + t2r * H1_STRIDE;
        const float* W20 = W2_t + tx2 * W2T_STRIDE;
        #pragma unroll 4
        for (int j4 = 0; j4 < D1; j4 += 4) {
            ulonglong2 a0 = *reinterpret_cast<const ulonglong2*>(Hp + j4);
            ulonglong2 a1 = *reinterpret_cast<const ulonglong2*>(Hp + H1_STRIDE + j4);
            #pragma unroll
            for (int m = 0; m < 5; m++) {
                ulonglong2 w = *reinterpret_cast<const ulonglong2*>(W20 + (8 * m) * W2T_STRIDE + j4);
                acc2[0][m] = ffma2(a0.x, w.x, acc2[0][m]);
                acc2[0][m] = ffma2(a0.y, w.y, acc2[0][m]);
                acc2[1][m] = ffma2(a1.x, w.x, acc2[1][m]);
                acc2[1][m] = ffma2(a1.y, w.y, acc2[1][m]);
            }
        }
        float ps0 = 0.f, ps1 = 0.f;
        #pragma unroll
        for (int m = 0; m < 5; m++) {
            int n = tx2 + 8 * m;
            float bb = b2_s[n], ww = Wd_s[n];
            float h20 = 1.f / (1.f + __expf(-(pair_sum(acc2[0][m]) + bb)));
            float h21 = 1.f / (1.f + __expf(-(pair_sum(acc2[1][m]) + bb)));
            ps0 += h20 * ww;
            ps1 += h21 * ww;
        }
        #pragma unroll
        for (int m = 1; m < 8; m <<= 1) {
            ps0 += __shfl_xor_sync(0xffffffffu, ps0, m);
            ps1 += __shfl_xor_sync(0xffffffffu, ps1, m);
        }
        if (tx2 == 0) {
            int tg = t0 + t2r;
            if (tg < T_DIM)     sc[tg]     = ps0;
            if (tg + 1 < T_DIM) sc[tg + 1] = ps1;
        }
    }
    __syncthreads();

    // ---- softmax over valid positions (scale 1/sqrt(64), bd cancels) ----
    float v = -INFINITY;
    if (tid < len) v = sc[tid] * 0.125f;
    float m = v;
    #pragma unroll
    for (int s = 16; s; s >>= 1) m = fmaxf(m, __shfl_xor_sync(0xffffffffu, m, s));
    if ((tid & 31) == 0) red[tid >> 5] = m;
    __syncthreads();
    if (tid == 0) {
        float mm = red[0];
        #pragma unroll
        for (int i = 1; i < 8; i++) mm = fmaxf(mm, red[i]);
        red[0] = mm;
    }
    __syncthreads();
    const float M = red[0];

    float e = (tid < len) ? __expf(v - M) : 0.f;
    float s = e;
    #pragma unroll
    for (int w = 16; w; w >>= 1) s += __shfl_xor_sync(0xffffffffu, s, w);
    if ((tid & 31) == 0) red2[tid >> 5] = s;
    __syncthreads();
    if (tid == 0) {
        float ss = red2[0];
        #pragma unroll
        for (int i = 1; i < 8; i++) ss += red2[i];
        red2[0] = ss;
    }
    __syncthreads();
    const float inv_sum = 1.f / red2[0];
    if (tid < T_DIM) sc[tid] = e * inv_sum;
    __syncthreads();

    // ---- out[h] = sum_t att[t] * keys[b,t,h] ----
    {
        const int g  = tid >> 6;   // 0..3
        const int hh = tid & 63;
        float acc = 0.f;
        for (int t = g; t < len; t += 4)
            acc += sc[t] * Kbase[t * H_DIM + hh];
        obuf[tid] = acc;
        __syncthreads();
        if (tid < H_DIM)
            out[b * H_DIM + tid] =
                obuf[tid] + obuf[64 + tid] + obuf[128 + tid] + obuf[192 + tid];
    }
}

extern "C" void kernel_launch(void* const* d_in, const int* in_sizes, int n_in,
                              void* d_out, int out_size)
{
    const float* queries = (const float*)d_in[0];
    const float* keys    = (const float*)d_in[1];
    const int*   klen    = (const int*)d_in[2];
    const float* W1      = (const float*)d_in[3];
    const float* b1      = (const float*)d_in[4];
    const float* W2      = (const float*)d_in[5];
    const float* b2      = (const float*)d_in[6];
    const float* Wd      = (const float*)d_in[7];
    // d_in[8] = bd : uniform shift, cancels in softmax
    float* out = (float*)d_out;

    const int B = in_sizes[2];  // keys_length count
    const size_t smem = SMEM_FLOATS * sizeof(float);
    cudaFuncSetAttribute(seqatt_kernel,
                         cudaFuncAttributeMaxDynamicSharedMemorySize, (int)smem);
    seqatt_kernel<<<B, 256, smem>>>(queries, keys, klen, W1, b1, W2, b2, Wd, out);
}

// round 5
// speedup vs baseline: 1.9385x; 1.5458x over previous
#include <cuda_runtime.h>
#include <math.h>
#include <stdint.h>

// SequenceAttLayer: B=4096, T=200, H=64; MLP 256->80->40->1, masked softmax, att@keys.
// Algebra: x=[q,k,q-k,q*k];  x.W1 = k.(W1b-W1c + diag(q).W1d) + [q.(W1a+W1c)+b1]
// Round 5: both MLP GEMMs on tensor cores via mma.sync m16n8k8 tf32.
// S region [64][84] holds the K chunk (tf32) during layer1, then H1 (tf32) for layer2.

#define T_DIM 200
#define H_DIM 64
#define D1 80
#define D2 40

#define S_STRIDE   84   // K tile / H1 tile rows; (20*gid+tig)%32 all-distinct
#define WT_STRIDE  68   // W_t [j][h]; (4*gid+tig)%32 all-distinct

// shared layout (floats)
#define OFF_S      0                 // 64*84 = 5376
#define OFF_WT     5376              // 80*68 = 5440
#define OFF_W2     10816             // 80*40 = 3200
#define OFF_C      14016             // 80
#define OFF_B2     14096             // 40
#define OFF_WD     14136             // 40
#define OFF_Q      14176             // 64
#define OFF_SC     14240             // 200
#define OFF_RED    14440             // 8
#define OFF_RED2   14448             // 8
#define OFF_PART   14456             // 128
#define OFF_OBUF   14584             // 256
#define SMEM_FLOATS 14840            // 59360 B -> 3 CTAs/SM

__device__ __forceinline__ float tf32r(float f) {
    uint32_t r;
    asm("cvt.rna.tf32.f32 %0, %1;" : "=r"(r) : "f"(f));
    return __uint_as_float(r);
}

__device__ __forceinline__ void mma8(float& d0, float& d1, float& d2, float& d3,
                                     uint32_t a0, uint32_t a1, uint32_t a2, uint32_t a3,
                                     uint32_t b0, uint32_t b1) {
    asm("mma.sync.aligned.m16n8k8.row.col.f32.tf32.tf32.f32 "
        "{%0,%1,%2,%3}, {%4,%5,%6,%7}, {%8,%9}, {%0,%1,%2,%3};"
        : "+f"(d0), "+f"(d1), "+f"(d2), "+f"(d3)
        : "r"(a0), "r"(a1), "r"(a2), "r"(a3), "r"(b0), "r"(b1));
}

__device__ __forceinline__ float sigf(float z) {
    return 1.f / (1.f + __expf(-z));
}

// Layer-2 tile worker: NT n-tiles starting at ntOff; A = H1 in S, B = W2_s [j][n].
template <int NT>
__device__ __forceinline__ void layer2_tiles(
    const float* __restrict__ S, const float* __restrict__ W2_s,
    const float* __restrict__ b2_s, const float* __restrict__ Wd_s,
    int arow, int gid, int tig, int ntOff, float& s0, float& s1)
{
    float acc[NT][4];
    #pragma unroll
    for (int nt = 0; nt < NT; nt++)
        #pragma unroll
        for (int i = 0; i < 4; i++) acc[nt][i] = 0.f;

    #pragma unroll
    for (int ks = 0; ks < 10; ks++) {
        int c0 = 8 * ks + tig;
        uint32_t A0 = __float_as_uint(S[arow * S_STRIDE + c0]);
        uint32_t A1 = __float_as_uint(S[(arow + 8) * S_STRIDE + c0]);
        uint32_t A2 = __float_as_uint(S[arow * S_STRIDE + c0 + 4]);
        uint32_t A3 = __float_as_uint(S[(arow + 8) * S_STRIDE + c0 + 4]);
        #pragma unroll
        for (int nt = 0; nt < NT; nt++) {
            int n = 8 * (ntOff + nt) + gid;
            uint32_t B0 = __float_as_uint(W2_s[c0 * D2 + n]);
            uint32_t B1 = __float_as_uint(W2_s[(c0 + 4) * D2 + n]);
            mma8(acc[nt][0], acc[nt][1], acc[nt][2], acc[nt][3],
                 A0, A1, A2, A3, B0, B1);
        }
    }
    s0 = 0.f; s1 = 0.f;
    #pragma unroll
    for (int nt = 0; nt < NT; nt++) {
        int n0 = 8 * (ntOff + nt) + 2 * tig;
        float2 bb = *reinterpret_cast<const float2*>(b2_s + n0);
        float2 wd = *reinterpret_cast<const float2*>(Wd_s + n0);
        s0 += sigf(acc[nt][0] + bb.x) * wd.x + sigf(acc[nt][1] + bb.y) * wd.y;
        s1 += sigf(acc[nt][2] + bb.x) * wd.x + sigf(acc[nt][3] + bb.y) * wd.y;
    }
}

__global__ __launch_bounds__(256, 3)
void seqatt_kernel(const float* __restrict__ queries,
                   const float* __restrict__ keys,
                   const int* __restrict__ keys_length,
                   const float* __restrict__ W1,
                   const float* __restrict__ b1,
                   const float* __restrict__ W2,
                   const float* __restrict__ b2,
                   const float* __restrict__ Wd,
                   float* __restrict__ out)
{
    extern __shared__ float sm[];
    float* S     = sm + OFF_S;
    float* W_t   = sm + OFF_WT;
    float* W2_s  = sm + OFF_W2;
    float* c_s   = sm + OFF_C;
    float* b2_s  = sm + OFF_B2;
    float* Wd_s  = sm + OFF_WD;
    float* q_s   = sm + OFF_Q;
    float* sc    = sm + OFF_SC;
    float* red   = sm + OFF_RED;
    float* red2  = sm + OFF_RED2;
    float* part  = sm + OFF_PART;
    float* obuf  = sm + OFF_OBUF;

    const int b   = blockIdx.x;
    const int tid = threadIdx.x;
    // keys_length is int32 on device (JAX x64-disabled downcasts int64->int32).
    int len = keys_length[b];
    len = len < 1 ? 1 : (len > T_DIM ? T_DIM : len);

    // ---- phase 0: stage q, weights (tf32); build W_t and c ----
    if (tid < H_DIM) q_s[tid] = queries[b * H_DIM + tid];
    if (tid < D2) { b2_s[tid] = b2[tid]; Wd_s[tid] = Wd[tid]; }
    for (int i = tid; i < D1 * D2; i += 256) W2_s[i] = tf32r(W2[i]);
    __syncthreads();

    // W_t[j][h] = tf32( W1b[h][j] - W1c[h][j] + q[h]*W1d[h][j] )
    for (int i = tid; i < H_DIM * D1; i += 256) {
        int h = i / D1, j = i - h * D1;
        float wb = W1[(64  + h) * D1 + j];
        float wc = W1[(128 + h) * D1 + j];
        float wd = W1[(192 + h) * D1 + j];
        W_t[j * WT_STRIDE + h] = tf32r(wb - wc + q_s[h] * wd);
    }
    if (tid < D1) {
        float acc = b1[tid];
        #pragma unroll 8
        for (int h = 0; h < H_DIM; h++)
            acc += q_s[h] * (W1[h * D1 + tid] + W1[(128 + h) * D1 + tid]);
        c_s[tid] = acc;
    }

    const int w    = tid >> 5;
    const int lane = tid & 31;
    const int gid  = lane >> 2;    // 0..7
    const int tig  = lane & 3;     // 0..3
    const int m    = w & 3;        // m-tile (both layers)
    const int arow = 16 * m + gid; // fragment row within chunk
    const int ntb0 = (w >> 2) * 5; // layer1 n-tile base (0 or 5)

    const float* Kbase = keys + (size_t)b * T_DIM * H_DIM;
    const int nchunk = (len + 63) >> 6;

    for (int ch = 0; ch < nchunk; ch++) {
        const int t0 = ch << 6;
        __syncthreads();   // phase0 done (ch0) / prev layer2 done reading S (ch>0)

        // ---- stage K chunk [64][64] -> S as tf32 (row clamped; tail masked later) ----
        for (int i = tid; i < 1024; i += 256) {
            int e = i << 2;
            int t = e >> 6, c = e & 63;
            int tg = t0 + t;
            int row = tg < T_DIM ? tg : T_DIM - 1;
            float4 f = *reinterpret_cast<const float4*>(Kbase + row * H_DIM + c);
            f.x = tf32r(f.x); f.y = tf32r(f.y); f.z = tf32r(f.z); f.w = tf32r(f.w);
            *reinterpret_cast<float4*>(S + t * S_STRIDE + c) = f;
        }
        __syncthreads();

        // ---- layer 1: [64x80] = K[64x64] @ W_eff[64x80] + c, then sigmoid ----
        float acc1[5][4];
        #pragma unroll
        for (int nt = 0; nt < 5; nt++)
            #pragma unroll
            for (int i = 0; i < 4; i++) acc1[nt][i] = 0.f;

        #pragma unroll
        for (int ks = 0; ks < 8; ks++) {
            int c0 = 8 * ks + tig;
            uint32_t A0 = __float_as_uint(S[arow * S_STRIDE + c0]);
            uint32_t A1 = __float_as_uint(S[(arow + 8) * S_STRIDE + c0]);
            uint32_t A2 = __float_as_uint(S[arow * S_STRIDE + c0 + 4]);
            uint32_t A3 = __float_as_uint(S[(arow + 8) * S_STRIDE + c0 + 4]);
            #pragma unroll
            for (int nt = 0; nt < 5; nt++) {
                int n = 8 * (ntb0 + nt) + gid;
                uint32_t B0 = __float_as_uint(W_t[n * WT_STRIDE + c0]);
                uint32_t B1 = __float_as_uint(W_t[n * WT_STRIDE + c0 + 4]);
                mma8(acc1[nt][0], acc1[nt][1], acc1[nt][2], acc1[nt][3],
                     A0, A1, A2, A3, B0, B1);
            }
        }
        // sigmoid (+c) into registers, tf32-rounded for layer2
        #pragma unroll
        for (int nt = 0; nt < 5; nt++) {
            int n0 = 8 * (ntb0 + nt) + 2 * tig;
            float2 cc = *reinterpret_cast<const float2*>(c_s + n0);
            acc1[nt][0] = tf32r(sigf(acc1[nt][0] + cc.x));
            acc1[nt][1] = tf32r(sigf(acc1[nt][1] + cc.y));
            acc1[nt][2] = tf32r(sigf(acc1[nt][2] + cc.x));
            acc1[nt][3] = tf32r(sigf(acc1[nt][3] + cc.y));
        }
        __syncthreads();   // everyone done reading K from S

        // ---- store H1 into S [t][j] ----
        #pragma unroll
        for (int nt = 0; nt < 5; nt++) {
            int n0 = 8 * (ntb0 + nt) + 2 * tig;
            *reinterpret_cast<float2*>(S + arow * S_STRIDE + n0) =
                make_float2(acc1[nt][0], acc1[nt][1]);
            *reinterpret_cast<float2*>(S + (arow + 8) * S_STRIDE + n0) =
                make_float2(acc1[nt][2], acc1[nt][3]);
        }
        __syncthreads();

        // ---- layer 2 + head: [64x40] = H1 @ W2, sigmoid, dot Wd ----
        float s0, s1;
        if (w < 4) layer2_tiles<3>(S, W2_s, b2_s, Wd_s, arow, gid, tig, 0, s0, s1);
        else       layer2_tiles<2>(S, W2_s, b2_s, Wd_s, arow, gid, tig, 3, s0, s1);
        // reduce across tig (lane bits 0..1)
        #pragma unroll
        for (int off = 1; off < 4; off <<= 1) {
            s0 += __shfl_xor_sync(0xffffffffu, s0, off);
            s1 += __shfl_xor_sync(0xffffffffu, s1, off);
        }
        if (tig == 0) {
            int half = (w >> 2) * 64;
            part[half + 16 * m + gid]     = s0;
            part[half + 16 * m + gid + 8] = s1;
        }
        __syncthreads();

        if (tid < 64) {
            int tg = t0 + tid;
            if (tg < T_DIM) sc[tg] = part[tid] + part[64 + tid];
        }
    }
    __syncthreads();

    // ---- softmax over valid positions (scale 1/sqrt(64), bd cancels) ----
    float v = -INFINITY;
    if (tid < len) v = sc[tid] * 0.125f;
    float mx = v;
    #pragma unroll
    for (int s = 16; s; s >>= 1) mx = fmaxf(mx, __shfl_xor_sync(0xffffffffu, mx, s));
    if ((tid & 31) == 0) red[tid >> 5] = mx;
    __syncthreads();
    if (tid == 0) {
        float mm = red[0];
        #pragma unroll
        for (int i = 1; i < 8; i++) mm = fmaxf(mm, red[i]);
        red[0] = mm;
    }
    __syncthreads();
    const float M = red[0];

    float e = (tid < len) ? __expf(v - M) : 0.f;
    float s = e;
    #pragma unroll
    for (int o = 16; o; o >>= 1) s += __shfl_xor_sync(0xffffffffu, s, o);
    if ((tid & 31) == 0) red2[tid >> 5] = s;
    __syncthreads();
    if (tid == 0) {
        float ss = red2[0];
        #pragma unroll
        for (int i = 1; i < 8; i++) ss += red2[i];
        red2[0] = ss;
    }
    __syncthreads();
    const float inv_sum = 1.f / red2[0];
    if (tid < T_DIM) sc[tid] = e * inv_sum;
    __syncthreads();

    // ---- out[h] = sum_t att[t] * keys[b,t,h] ----
    {
        const int g  = tid >> 6;   // 0..3
        const int hh = tid & 63;
        float acc = 0.f;
        for (int t = g; t < len; t += 4)
            acc += sc[t] * Kbase[t * H_DIM + hh];
        obuf[tid] = acc;
        __syncthreads();
        if (tid < H_DIM)
            out[b * H_DIM + tid] =
                obuf[tid] + obuf[64 + tid] + obuf[128 + tid] + obuf[192 + tid];
    }
}

extern "C" void kernel_launch(void* const* d_in, const int* in_sizes, int n_in,
                              void* d_out, int out_size)
{
    const float* queries = (const float*)d_in[0];
    const float* keys    = (const float*)d_in[1];
    const int*   klen    = (const int*)d_in[2];
    const float* W1      = (const float*)d_in[3];
    const float* b1      = (const float*)d_in[4];
    const float* W2      = (const float*)d_in[5];
    const float* b2      = (const float*)d_in[6];
    const float* Wd      = (const float*)d_in[7];
    // d_in[8] = bd : uniform shift, cancels in softmax
    float* out = (float*)d_out;

    const int B = in_sizes[2];  // keys_length count
    const size_t smem = SMEM_FLOATS * sizeof(float);
    cudaFuncSetAttribute(seqatt_kernel,
                         cudaFuncAttributeMaxDynamicSharedMemorySize, (int)smem);
    seqatt_kernel<<<B, 256, smem>>>(queries, keys, klen, W1, b1, W2, b2, Wd, out);
}

// round 6
// speedup vs baseline: 2.7308x; 1.4087x over previous
#include <cuda_runtime.h>
#include <cuda_bf16.h>
#include <math.h>
#include <stdint.h>

// SequenceAttLayer: B=4096, T=200, H=64; MLP 256->80->40->1, masked softmax, att@keys.
// Algebra: x=[q,k,q-k,q*k];  x.W1 = k.(W1b-W1c + diag(q).W1d) + [q.(W1a+W1c)+b1]
// Round 6: bf16 m16n8k16 mma + ldmatrix fragment loads, fp32 accum/epilogues,
// 4 CTAs/SM (smem 41.3KB, 64-reg cap).

#define T_DIM 200
#define H_DIM 64
#define D1 80
#define D2 40

// strides in bf16 elements (row byte deltas 144/176 -> ldmatrix conflict-free)
#define K_STR   72   // K_s  [t][h]
#define H1_STR  88   // H1_s [t][j]
#define WT_STR  72   // W_t  [j][h]   (B of layer1: [n][k])
#define W2T_STR 88   // W2_t [n][j]   (B of layer2: [n][k])

// shared layout (float offsets; bf16 regions are 2x elements)
#define OFF_KS    0        // 64*72 bf16  = 2304 f
#define OFF_H1    2304     // 64*88 bf16  = 2816 f
#define OFF_WT    5120     // 80*72 bf16  = 2880 f
#define OFF_W2T   8000     // 40*88 bf16  = 1760 f
#define OFF_C     9760     // 80
#define OFF_B2    9840     // 40
#define OFF_WD    9880     // 40
#define OFF_Q     9920     // 64
#define OFF_SC    9984     // 200
#define OFF_RED   10184    // 8
#define OFF_RED2  10192    // 8
#define OFF_PART  10200    // 128
#define OFF_OBUF  10328    // 256
#define SMEM_FLOATS 10584  // 42336 B -> 4 CTAs/SM

typedef __nv_bfloat16 bf16;

__device__ __forceinline__ uint32_t cvsm(const void* p) {
    return (uint32_t)__cvta_generic_to_shared(p);
}
__device__ __forceinline__ void ldm_x4(uint32_t& r0, uint32_t& r1,
                                       uint32_t& r2, uint32_t& r3, uint32_t a) {
    asm volatile("ldmatrix.sync.aligned.m8n8.x4.shared.b16 {%0,%1,%2,%3}, [%4];"
                 : "=r"(r0), "=r"(r1), "=r"(r2), "=r"(r3) : "r"(a));
}
__device__ __forceinline__ void ldm_x2(uint32_t& r0, uint32_t& r1, uint32_t a) {
    asm volatile("ldmatrix.sync.aligned.m8n8.x2.shared.b16 {%0,%1}, [%2];"
                 : "=r"(r0), "=r"(r1) : "r"(a));
}
__device__ __forceinline__ void mma16(float& d0, float& d1, float& d2, float& d3,
                                      uint32_t a0, uint32_t a1, uint32_t a2, uint32_t a3,
                                      uint32_t b0, uint32_t b1) {
    asm("mma.sync.aligned.m16n8k16.row.col.f32.bf16.bf16.f32 "
        "{%0,%1,%2,%3}, {%4,%5,%6,%7}, {%8,%9}, {%0,%1,%2,%3};"
        : "+f"(d0), "+f"(d1), "+f"(d2), "+f"(d3)
        : "r"(a0), "r"(a1), "r"(a2), "r"(a3), "r"(b0), "r"(b1));
}
__device__ __forceinline__ uint32_t pack_bf16(float lo, float hi) {
    uint32_t r;
    asm("cvt.rn.bf16x2.f32 %0, %1, %2;" : "=r"(r) : "f"(hi), "f"(lo));
    return r;
}
__device__ __forceinline__ float sigf(float z) { return 1.f / (1.f + __expf(-z)); }

__global__ __launch_bounds__(256, 4)
void seqatt_kernel(const float* __restrict__ queries,
                   const float* __restrict__ keys,
                   const int* __restrict__ keys_length,
                   const float* __restrict__ W1,
                   const float* __restrict__ b1,
                   const float* __restrict__ W2,
                   const float* __restrict__ b2,
                   const float* __restrict__ Wd,
                   float* __restrict__ out)
{
    extern __shared__ float sm[];
    bf16* K_s   = reinterpret_cast<bf16*>(sm + OFF_KS);
    bf16* H1_s  = reinterpret_cast<bf16*>(sm + OFF_H1);
    bf16* W_t   = reinterpret_cast<bf16*>(sm + OFF_WT);
    bf16* W2_t  = reinterpret_cast<bf16*>(sm + OFF_W2T);
    float* c_s  = sm + OFF_C;
    float* b2_s = sm + OFF_B2;
    float* Wd_s = sm + OFF_WD;
    float* q_s  = sm + OFF_Q;
    float* sc   = sm + OFF_SC;
    float* red  = sm + OFF_RED;
    float* red2 = sm + OFF_RED2;
    float* part = sm + OFF_PART;
    float* obuf = sm + OFF_OBUF;

    const int b   = blockIdx.x;
    const int tid = threadIdx.x;
    // keys_length is int32 on device (JAX x64-disabled downcasts int64->int32).
    int len = keys_length[b];
    len = len < 1 ? 1 : (len > T_DIM ? T_DIM : len);

    // ---- phase 0: stage q, b2, Wd, W2_t; then build W_t (bf16) and c (fp32) ----
    if (tid < H_DIM) q_s[tid] = queries[b * H_DIM + tid];
    if (tid < D2) { b2_s[tid] = b2[tid]; Wd_s[tid] = Wd[tid]; }
    for (int i = tid; i < D1 * D2; i += 256) {       // W2_t[n][j] = W2[j][n]
        int j = i / D2, n = i - j * D2;
        W2_t[n * W2T_STR + j] = __float2bfloat16(W2[i]);
    }
    __syncthreads();

    for (int i = tid; i < H_DIM * D1; i += 256) {    // W_t[j][h]
        int h = i / D1, j = i - h * D1;
        float wb = W1[(64  + h) * D1 + j];
        float wc = W1[(128 + h) * D1 + j];
        float wd = W1[(192 + h) * D1 + j];
        W_t[j * WT_STR + h] = __float2bfloat16(wb - wc + q_s[h] * wd);
    }
    if (tid < D1) {
        float acc = b1[tid];
        #pragma unroll 8
        for (int h = 0; h < H_DIM; h++)
            acc += q_s[h] * (W1[h * D1 + tid] + W1[(128 + h) * D1 + tid]);
        c_s[tid] = acc;
    }

    const int w    = tid >> 5;
    const int lane = tid & 31;
    const int gid  = lane >> 2;       // 0..7
    const int tig  = lane & 3;        // 0..3
    const int m    = w & 3;           // m-tile: rows 16m..16m+15
    const int arow = 16 * m + gid;
    const int ntb0 = (w >> 2) * 5;    // layer1 n-tile base: 0 or 5 (of 10)
    const int ntO2 = (w >> 2) * 3;    // layer2 n-tile base: 0 or 3 (of 5)

    // ldmatrix lane address components
    const int r8  = lane & 7;         // row within 8x8 tile
    const int mi  = lane >> 3;        // matrix index 0..3
    const int mi2 = mi & 1;

    // A-fragment addresses (x4: m0/m1 = rows 0-7/8-15 of k0-7; m2/m3 same of k8-15)
    const uint32_t aA1 = cvsm(K_s)  + 2 * ((16 * m + r8 + ((mi & 1) << 3)) * K_STR  + ((mi >> 1) << 3));
    const uint32_t aA2 = cvsm(H1_s) + 2 * ((16 * m + r8 + ((mi & 1) << 3)) * H1_STR + ((mi >> 1) << 3));
    // B layer1 (x4 covers 2 n-tiles: m0/m1 = b0/b1 of nt; m2/m3 = of nt+1)
    const uint32_t aB01 = cvsm(W_t) + 2 * ((8 * (ntb0 + (mi >> 1)) + r8) * WT_STR + ((mi & 1) << 3));
    const uint32_t aB23 = aB01 + 2 * (16 * WT_STR);
    const uint32_t aB4  = cvsm(W_t) + 2 * ((8 * (ntb0 + 4) + r8) * WT_STR + (mi2 << 3));
    // B layer2
    const uint32_t aC01 = cvsm(W2_t) + 2 * ((8 * (ntO2 + (mi >> 1)) + r8) * W2T_STR + ((mi & 1) << 3));
    const uint32_t aC2  = cvsm(W2_t) + 2 * ((8 * (ntO2 + 2) + r8) * W2T_STR + (mi2 << 3));

    const float* Kbase = keys + (size_t)b * T_DIM * H_DIM;
    const int nchunk = (len + 63) >> 6;

    for (int ch = 0; ch < nchunk; ch++) {
        const int t0 = ch << 6;

        // ---- stage K chunk [64][64] -> K_s bf16 (row clamp; tail masked later) ----
        for (int i = tid; i < 1024; i += 256) {
            int e = i << 2;
            int t = e >> 6, c = e & 63;
            int tg = t0 + t;
            int row = tg < T_DIM ? tg : T_DIM - 1;
            float4 f = *reinterpret_cast<const float4*>(Kbase + row * H_DIM + c);
            uint2 u;
            u.x = pack_bf16(f.x, f.y);
            u.y = pack_bf16(f.z, f.w);
            *reinterpret_cast<uint2*>(K_s + t * K_STR + c) = u;
        }
        __syncthreads();   // K_s ready; (ch0) also fences phase-0 W_t/c writes

        // ---- layer 1: [64x80] = K @ W_eff + c, sigmoid -> H1_s (bf16) ----
        float acc1[5][4];
        #pragma unroll
        for (int nt = 0; nt < 5; nt++)
            #pragma unroll
            for (int i = 0; i < 4; i++) acc1[nt][i] = 0.f;

        #pragma unroll
        for (int ks = 0; ks < 4; ks++) {
            const uint32_t off = 32 * ks;   // 16 bf16 in k
            uint32_t a0, a1, a2, a3;
            ldm_x4(a0, a1, a2, a3, aA1 + off);
            uint32_t b0, b1, b2r, b3, b4, b5;
            ldm_x4(b0, b1, b2r, b3, aB01 + off);
            mma16(acc1[0][0], acc1[0][1], acc1[0][2], acc1[0][3], a0, a1, a2, a3, b0, b1);
            mma16(acc1[1][0], acc1[1][1], acc1[1][2], acc1[1][3], a0, a1, a2, a3, b2r, b3);
            ldm_x4(b0, b1, b2r, b3, aB23 + off);
            mma16(acc1[2][0], acc1[2][1], acc1[2][2], acc1[2][3], a0, a1, a2, a3, b0, b1);
            mma16(acc1[3][0], acc1[3][1], acc1[3][2], acc1[3][3], a0, a1, a2, a3, b2r, b3);
            ldm_x2(b4, b5, aB4 + off);
            mma16(acc1[4][0], acc1[4][1], acc1[4][2], acc1[4][3], a0, a1, a2, a3, b4, b5);
        }
        // sigmoid(+c) and store H1 (bf16); D-frag: d0/d1 = (arow, 2tig/2tig+1), d2/d3 = arow+8
        #pragma unroll
        for (int nt = 0; nt < 5; nt++) {
            int n0 = 8 * (ntb0 + nt) + 2 * tig;
            float2 cc = *reinterpret_cast<const float2*>(c_s + n0);
            uint32_t lo = pack_bf16(sigf(acc1[nt][0] + cc.x), sigf(acc1[nt][1] + cc.y));
            uint32_t hi = pack_bf16(sigf(acc1[nt][2] + cc.x), sigf(acc1[nt][3] + cc.y));
            *reinterpret_cast<uint32_t*>(H1_s + arow * H1_STR + n0) = lo;
            *reinterpret_cast<uint32_t*>(H1_s + (arow + 8) * H1_STR + n0) = hi;
        }
        __syncthreads();   // H1 ready

        // ---- layer 2 + head: [64x40] = H1 @ W2, sigmoid, dot Wd ----
        float s0 = 0.f, s1 = 0.f;
        if (w < 4) {
            float acc2[3][4];
            #pragma unroll
            for (int nt = 0; nt < 3; nt++)
                #pragma unroll
                for (int i = 0; i < 4; i++) acc2[nt][i] = 0.f;
            #pragma unroll
            for (int ks = 0; ks < 5; ks++) {
                const uint32_t off = 32 * ks;
                uint32_t a0, a1, a2, a3, b0, b1, b2r, b3;
                ldm_x4(a0, a1, a2, a3, aA2 + off);
                ldm_x4(b0, b1, b2r, b3, aC01 + off);
                mma16(acc2[0][0], acc2[0][1], acc2[0][2], acc2[0][3], a0, a1, a2, a3, b0, b1);
                mma16(acc2[1][0], acc2[1][1], acc2[1][2], acc2[1][3], a0, a1, a2, a3, b2r, b3);
                ldm_x2(b0, b1, aC2 + off);
                mma16(acc2[2][0], acc2[2][1], acc2[2][2], acc2[2][3], a0, a1, a2, a3, b0, b1);
            }
            #pragma unroll
            for (int nt = 0; nt < 3; nt++) {
                int n0 = 8 * (ntO2 + nt) + 2 * tig;
                float2 bb = *reinterpret_cast<const float2*>(b2_s + n0);
                float2 wd = *reinterpret_cast<const float2*>(Wd_s + n0);
                s0 += sigf(acc2[nt][0] + bb.x) * wd.x + sigf(acc2[nt][1] + bb.y) * wd.y;
                s1 += sigf(acc2[nt][2] + bb.x) * wd.x + sigf(acc2[nt][3] + bb.y) * wd.y;
            }
        } else {
            float acc2[2][4];
            #pragma unroll
            for (int nt = 0; nt < 2; nt++)
                #pragma unroll
                for (int i = 0; i < 4; i++) acc2[nt][i] = 0.f;
            #pragma unroll
            for (int ks = 0; ks < 5; ks++) {
                const uint32_t off = 32 * ks;
                uint32_t a0, a1, a2, a3, b0, b1, b2r, b3;
                ldm_x4(a0, a1, a2, a3, aA2 + off);
                ldm_x4(b0, b1, b2r, b3, aC01 + off);
                mma16(acc2[0][0], acc2[0][1], acc2[0][2], acc2[0][3], a0, a1, a2, a3, b0, b1);
                mma16(acc2[1][0], acc2[1][1], acc2[1][2], acc2[1][3], a0, a1, a2, a3, b2r, b3);
            }
            #pragma unroll
            for (int nt = 0; nt < 2; nt++) {
                int n0 = 8 * (ntO2 + nt) + 2 * tig;
                float2 bb = *reinterpret_cast<const float2*>(b2_s + n0);
                float2 wd = *reinterpret_cast<const float2*>(Wd_s + n0);
                s0 += sigf(acc2[nt][0] + bb.x) * wd.x + sigf(acc2[nt][1] + bb.y) * wd.y;
                s1 += sigf(acc2[nt][2] + bb.x) * wd.x + sigf(acc2[nt][3] + bb.y) * wd.y;
            }
        }
        #pragma unroll
        for (int off = 1; off < 4; off <<= 1) {
            s0 += __shfl_xor_sync(0xffffffffu, s0, off);
            s1 += __shfl_xor_sync(0xffffffffu, s1, off);
        }
        if (tig == 0) {
            int half = (w >> 2) * 64;
            part[half + 16 * m + gid]     = s0;
            part[half + 16 * m + gid + 8] = s1;
        }
        __syncthreads();

        if (tid < 64) {
            int tg = t0 + tid;
            if (tg < T_DIM) sc[tg] = part[tid] + part[64 + tid];
        }
        __syncthreads();
    }

    // ---- softmax over valid positions (scale 1/sqrt(64), bd cancels) ----
    float v = -INFINITY;
    if (tid < len) v = sc[tid] * 0.125f;
    float mx = v;
    #pragma unroll
    for (int s = 16; s; s >>= 1) mx = fmaxf(mx, __shfl_xor_sync(0xffffffffu, mx, s));
    if ((tid & 31) == 0) red[tid >> 5] = mx;
    __syncthreads();
    if (tid == 0) {
        float mm = red[0];
        #pragma unroll
        for (int i = 1; i < 8; i++) mm = fmaxf(mm, red[i]);
        red[0] = mm;
    }
    __syncthreads();
    const float M = red[0];

    float e = (tid < len) ? __expf(v - M) : 0.f;
    float s = e;
    #pragma unroll
    for (int o = 16; o; o >>= 1) s += __shfl_xor_sync(0xffffffffu, s, o);
    if ((tid & 31) == 0) red2[tid >> 5] = s;
    __syncthreads();
    if (tid == 0) {
        float ss = red2[0];
        #pragma unroll
        for (int i = 1; i < 8; i++) ss += red2[i];
        red2[0] = ss;
    }
    __syncthreads();
    const float inv_sum = 1.f / red2[0];
    if (tid < T_DIM) sc[tid] = e * inv_sum;
    __syncthreads();

    // ---- out[h] = sum_t att[t] * keys[b,t,h]  (fp32 keys) ----
    {
        const int g  = tid >> 6;   // 0..3
        const int hh = tid & 63;
        float acc = 0.f;
        for (int t = g; t < len; t += 4)
            acc += sc[t] * Kbase[t * H_DIM + hh];
        obuf[tid] = acc;
        __syncthreads();
        if (tid < H_DIM)
            out[b * H_DIM + tid] =
                obuf[tid] + obuf[64 + tid] + obuf[128 + tid] + obuf[192 + tid];
    }
}

extern "C" void kernel_launch(void* const* d_in, const int* in_sizes, int n_in,
                              void* d_out, int out_size)
{
    const float* queries = (const float*)d_in[0];
    const float* keys    = (const float*)d_in[1];
    const int*   klen    = (const int*)d_in[2];
    const float* W1      = (const float*)d_in[3];
    const float* b1      = (const float*)d_in[4];
    const float* W2      = (const float*)d_in[5];
    const float* b2      = (const float*)d_in[6];
    const float* Wd      = (const float*)d_in[7];
    // d_in[8] = bd : uniform shift, cancels in softmax
    float* out = (float*)d_out;

    const int B = in_sizes[2];  // keys_length count
    const size_t smem = SMEM_FLOATS * sizeof(float);
    cudaFuncSetAttribute(seqatt_kernel,
                         cudaFuncAttributeMaxDynamicSharedMemorySize, (int)smem);
    seqatt_kernel<<<B, 256, smem>>>(queries, keys, klen, W1, b1, W2, b2, Wd, out);
}

// round 7
// speedup vs baseline: 3.3055x; 1.2104x over previous
#include <cuda_runtime.h>
#include <cuda_bf16.h>
#include <math.h>
#include <stdint.h>

// SequenceAttLayer: B=4096, T=200, H=64; MLP 256->80->40->1, masked softmax, att@keys.
// Algebra: x=[q,k,q-k,q*k];  x.W1 = k.(W1b-W1c + diag(q).W1d) + [q.(W1a+W1c)+b1]
// Round 7: bf16 m16n8k16 mma + ldmatrix; 2 barriers/chunk (deferred score combine),
// branch-free staging fast path, strength-reduced phase0/epilogue. 4 CTAs/SM.

#define T_DIM 200
#define H_DIM 64
#define D1 80
#define D2 40

// strides in bf16 elements (row byte deltas 144/176 -> ldmatrix conflict-free)
#define K_STR   72   // K_s  [t][h]
#define H1_STR  88   // H1_s [t][j]
#define WT_STR  72   // W_t  [j][h]   (B of layer1: [n][k])
#define W2T_STR 88   // W2_t [n][j]   (B of layer2: [n][k])

// shared layout (float offsets; bf16 regions are 2x elements)
#define OFF_KS    0        // 64*72 bf16  = 2304 f
#define OFF_H1    2304     // 64*88 bf16  = 2816 f
#define OFF_WT    5120     // 80*72 bf16  = 2880 f
#define OFF_W2T   8000     // 40*88 bf16  = 1760 f
#define OFF_C     9760     // 80
#define OFF_B2    9840     // 40
#define OFF_WD    9880     // 40
#define OFF_Q     9920     // 64
#define OFF_PART  9984     // 4 chunks * 128 = 512
#define OFF_SC    10496    // 200 (normalized att for output pass)
#define OFF_RED   10696    // 8
#define OFF_RED2  10704    // 8
#define OFF_OBUF  10712    // 256
#define SMEM_FLOATS 10968  // 43872 B -> 4 CTAs/SM

typedef __nv_bfloat16 bf16;

__device__ __forceinline__ uint32_t cvsm(const void* p) {
    return (uint32_t)__cvta_generic_to_shared(p);
}
__device__ __forceinline__ void ldm_x4(uint32_t& r0, uint32_t& r1,
                                       uint32_t& r2, uint32_t& r3, uint32_t a) {
    asm volatile("ldmatrix.sync.aligned.m8n8.x4.shared.b16 {%0,%1,%2,%3}, [%4];"
                 : "=r"(r0), "=r"(r1), "=r"(r2), "=r"(r3) : "r"(a));
}
__device__ __forceinline__ void ldm_x2(uint32_t& r0, uint32_t& r1, uint32_t a) {
    asm volatile("ldmatrix.sync.aligned.m8n8.x2.shared.b16 {%0,%1}, [%2];"
                 : "=r"(r0), "=r"(r1) : "r"(a));
}
__device__ __forceinline__ void mma16(float& d0, float& d1, float& d2, float& d3,
                                      uint32_t a0, uint32_t a1, uint32_t a2, uint32_t a3,
                                      uint32_t b0, uint32_t b1) {
    asm("mma.sync.aligned.m16n8k16.row.col.f32.bf16.bf16.f32 "
        "{%0,%1,%2,%3}, {%4,%5,%6,%7}, {%8,%9}, {%0,%1,%2,%3};"
        : "+f"(d0), "+f"(d1), "+f"(d2), "+f"(d3)
        : "r"(a0), "r"(a1), "r"(a2), "r"(a3), "r"(b0), "r"(b1));
}
__device__ __forceinline__ uint32_t pack_bf16(float lo, float hi) {
    uint32_t r;
    asm("cvt.rn.bf16x2.f32 %0, %1, %2;" : "=r"(r) : "f"(hi), "f"(lo));
    return r;
}
__device__ __forceinline__ float sigf(float z) { return 1.f / (1.f + __expf(-z)); }

__global__ __launch_bounds__(256, 4)
void seqatt_kernel(const float* __restrict__ queries,
                   const float* __restrict__ keys,
                   const int* __restrict__ keys_length,
                   const float* __restrict__ W1,
                   const float* __restrict__ b1,
                   const float* __restrict__ W2,
                   const float* __restrict__ b2,
                   const float* __restrict__ Wd,
                   float* __restrict__ out)
{
    extern __shared__ float sm[];
    bf16* K_s   = reinterpret_cast<bf16*>(sm + OFF_KS);
    bf16* H1_s  = reinterpret_cast<bf16*>(sm + OFF_H1);
    bf16* W_t   = reinterpret_cast<bf16*>(sm + OFF_WT);
    bf16* W2_t  = reinterpret_cast<bf16*>(sm + OFF_W2T);
    float* c_s  = sm + OFF_C;
    float* b2_s = sm + OFF_B2;
    float* Wd_s = sm + OFF_WD;
    float* q_s  = sm + OFF_Q;
    float* part = sm + OFF_PART;
    float* sc   = sm + OFF_SC;
    float* red  = sm + OFF_RED;
    float* red2 = sm + OFF_RED2;
    float* obuf = sm + OFF_OBUF;

    const int b   = blockIdx.x;
    const int tid = threadIdx.x;
    // keys_length is int32 on device (JAX x64-disabled downcasts int64->int32).
    int len = keys_length[b];
    len = len < 1 ? 1 : (len > T_DIM ? T_DIM : len);

    // ---- phase 0: stage q, b2, Wd, W2_t; then build W_t (bf16) and c (fp32) ----
    if (tid < H_DIM) q_s[tid] = queries[b * H_DIM + tid];
    if (tid < D2) { b2_s[tid] = b2[tid]; Wd_s[tid] = Wd[tid]; }
    // W2_t[n][j] = W2[j][n]; float2 over n
    for (int i = tid; i < D1 * (D2 / 2); i += 256) {
        int j = i / (D2 / 2), n2 = i - j * (D2 / 2);
        float2 v = *reinterpret_cast<const float2*>(W2 + j * D2 + 2 * n2);
        W2_t[(2 * n2)     * W2T_STR + j] = __float2bfloat16(v.x);
        W2_t[(2 * n2 + 1) * W2T_STR + j] = __float2bfloat16(v.y);
    }
    __syncthreads();

    // W_t[j][h] = W1b[h][j] - W1c[h][j] + q[h]*W1d[h][j]; float2 over j
    for (int i = tid; i < H_DIM * (D1 / 2); i += 256) {
        int h = i / (D1 / 2), j2 = i - h * (D1 / 2);
        float2 wb = *reinterpret_cast<const float2*>(W1 + (64  + h) * D1 + 2 * j2);
        float2 wc = *reinterpret_cast<const float2*>(W1 + (128 + h) * D1 + 2 * j2);
        float2 wd = *reinterpret_cast<const float2*>(W1 + (192 + h) * D1 + 2 * j2);
        float qh = q_s[h];
        W_t[(2 * j2)     * WT_STR + h] = __float2bfloat16(wb.x - wc.x + qh * wd.x);
        W_t[(2 * j2 + 1) * WT_STR + h] = __float2bfloat16(wb.y - wc.y + qh * wd.y);
    }
    if (tid < D1) {
        float acc = b1[tid];
        #pragma unroll 8
        for (int h = 0; h < H_DIM; h++)
            acc += q_s[h] * (W1[h * D1 + tid] + W1[(128 + h) * D1 + tid]);
        c_s[tid] = acc;
    }

    const int w    = tid >> 5;
    const int lane = tid & 31;
    const int gid  = lane >> 2;       // 0..7
    const int tig  = lane & 3;        // 0..3
    const int m    = w & 3;           // m-tile: rows 16m..16m+15
    const int arow = 16 * m + gid;
    const int ntb0 = (w >> 2) * 5;    // layer1 n-tile base: 0 or 5 (of 10)
    const int ntO2 = (w >> 2) * 3;    // layer2 n-tile base: 0 or 3 (of 5)

    // ldmatrix lane address components
    const int r8  = lane & 7;
    const int mi  = lane >> 3;
    const int mi2 = mi & 1;

    const uint32_t aA1 = cvsm(K_s)  + 2 * ((16 * m + r8 + ((mi & 1) << 3)) * K_STR  + ((mi >> 1) << 3));
    const uint32_t aA2 = cvsm(H1_s) + 2 * ((16 * m + r8 + ((mi & 1) << 3)) * H1_STR + ((mi >> 1) << 3));
    const uint32_t aB01 = cvsm(W_t) + 2 * ((8 * (ntb0 + (mi >> 1)) + r8) * WT_STR + ((mi & 1) << 3));
    const uint32_t aB23 = aB01 + 2 * (16 * WT_STR);
    const uint32_t aB4  = cvsm(W_t) + 2 * ((8 * (ntb0 + 4) + r8) * WT_STR + (mi2 << 3));
    const uint32_t aC01 = cvsm(W2_t) + 2 * ((8 * (ntO2 + (mi >> 1)) + r8) * W2T_STR + ((mi & 1) << 3));
    const uint32_t aC2  = cvsm(W2_t) + 2 * ((8 * (ntO2 + 2) + r8) * W2T_STR + (mi2 << 3));

    const float* Kbase = keys + (size_t)b * T_DIM * H_DIM;
    const int nchunk = (len + 63) >> 6;

    // per-thread staging geometry (fixed): row tid>>4 (+16/it), col 4*(tid&15)
    const int srow = tid >> 4;
    const int scol = (tid & 15) << 2;
    bf16* sdst0 = K_s + srow * K_STR + scol;
    const int phalf = (w >> 2) * 64;  // which n-half this warp contributes

    for (int ch = 0; ch < nchunk; ch++) {
        const int t0 = ch << 6;

        // ---- stage K chunk [64][64] -> K_s bf16 ----
        if (t0 + 64 <= T_DIM) {              // chunks 0..2: no clamp needed
            const float* g0 = Kbase + (t0 + srow) * H_DIM + scol;
            #pragma unroll
            for (int it = 0; it < 4; it++) {
                float4 f = *reinterpret_cast<const float4*>(g0 + it * (16 * H_DIM));
                uint2 u;
                u.x = pack_bf16(f.x, f.y);
                u.y = pack_bf16(f.z, f.w);
                *reinterpret_cast<uint2*>(sdst0 + it * (16 * K_STR)) = u;
            }
        } else {                              // tail chunk: clamp rows to T-1
            #pragma unroll
            for (int it = 0; it < 4; it++) {
                int tg = t0 + srow + 16 * it;
                int row = tg < T_DIM ? tg : T_DIM - 1;
                float4 f = *reinterpret_cast<const float4*>(Kbase + row * H_DIM + scol);
                uint2 u;
                u.x = pack_bf16(f.x, f.y);
                u.y = pack_bf16(f.z, f.w);
                *reinterpret_cast<uint2*>(sdst0 + it * (16 * K_STR)) = u;
            }
        }
        __syncthreads();   // K_s ready; (ch0) also fences phase-0 W_t/c writes

        // ---- layer 1: [64x80] = K @ W_eff + c, sigmoid -> H1_s (bf16) ----
        float acc1[5][4];
        #pragma unroll
        for (int nt = 0; nt < 5; nt++)
            #pragma unroll
            for (int i = 0; i < 4; i++) acc1[nt][i] = 0.f;

        #pragma unroll
        for (int ks = 0; ks < 4; ks++) {
            const uint32_t off = 32 * ks;
            uint32_t a0, a1, a2, a3;
            ldm_x4(a0, a1, a2, a3, aA1 + off);
            uint32_t b0, b1, b2r, b3, b4, b5;
            ldm_x4(b0, b1, b2r, b3, aB01 + off);
            mma16(acc1[0][0], acc1[0][1], acc1[0][2], acc1[0][3], a0, a1, a2, a3, b0, b1);
            mma16(acc1[1][0], acc1[1][1], acc1[1][2], acc1[1][3], a0, a1, a2, a3, b2r, b3);
            ldm_x4(b0, b1, b2r, b3, aB23 + off);
            mma16(acc1[2][0], acc1[2][1], acc1[2][2], acc1[2][3], a0, a1, a2, a3, b0, b1);
            mma16(acc1[3][0], acc1[3][1], acc1[3][2], acc1[3][3], a0, a1, a2, a3, b2r, b3);
            ldm_x2(b4, b5, aB4 + off);
            mma16(acc1[4][0], acc1[4][1], acc1[4][2], acc1[4][3], a0, a1, a2, a3, b4, b5);
        }
        #pragma unroll
        for (int nt = 0; nt < 5; nt++) {
            int n0 = 8 * (ntb0 + nt) + 2 * tig;
            float2 cc = *reinterpret_cast<const float2*>(c_s + n0);
            uint32_t lo = pack_bf16(sigf(acc1[nt][0] + cc.x), sigf(acc1[nt][1] + cc.y));
            uint32_t hi = pack_bf16(sigf(acc1[nt][2] + cc.x), sigf(acc1[nt][3] + cc.y));
            *reinterpret_cast<uint32_t*>(H1_s + arow * H1_STR + n0) = lo;
            *reinterpret_cast<uint32_t*>(H1_s + (arow + 8) * H1_STR + n0) = hi;
        }
        __syncthreads();   // H1 ready (also: all K_s reads done -> next staging safe)

        // ---- layer 2 + head: [64x40] = H1 @ W2, sigmoid, dot Wd ----
        float s0 = 0.f, s1 = 0.f;
        if (w < 4) {
            float acc2[3][4];
            #pragma unroll
            for (int nt = 0; nt < 3; nt++)
                #pragma unroll
                for (int i = 0; i < 4; i++) acc2[nt][i] = 0.f;
            #pragma unroll
            for (int ks = 0; ks < 5; ks++) {
                const uint32_t off = 32 * ks;
                uint32_t a0, a1, a2, a3, b0, b1, b2r, b3;
                ldm_x4(a0, a1, a2, a3, aA2 + off);
                ldm_x4(b0, b1, b2r, b3, aC01 + off);
                mma16(acc2[0][0], acc2[0][1], acc2[0][2], acc2[0][3], a0, a1, a2, a3, b0, b1);
                mma16(acc2[1][0], acc2[1][1], acc2[1][2], acc2[1][3], a0, a1, a2, a3, b2r, b3);
                ldm_x2(b0, b1, aC2 + off);
                mma16(acc2[2][0], acc2[2][1], acc2[2][2], acc2[2][3], a0, a1, a2, a3, b0, b1);
            }
            #pragma unroll
            for (int nt = 0; nt < 3; nt++) {
                int n0 = 8 * (ntO2 + nt) + 2 * tig;
                float2 bb = *reinterpret_cast<const float2*>(b2_s + n0);
                float2 wd = *reinterpret_cast<const float2*>(Wd_s + n0);
                s0 += sigf(acc2[nt][0] + bb.x) * wd.x + sigf(acc2[nt][1] + bb.y) * wd.y;
                s1 += sigf(acc2[nt][2] + bb.x) * wd.x + sigf(acc2[nt][3] + bb.y) * wd.y;
            }
        } else {
            float acc2[2][4];
            #pragma unroll
            for (int nt = 0; nt < 2; nt++)
                #pragma unroll
                for (int i = 0; i < 4; i++) acc2[nt][i] = 0.f;
            #pragma unroll
            for (int ks = 0; ks < 5; ks++) {
                const uint32_t off = 32 * ks;
                uint32_t a0, a1, a2, a3, b0, b1, b2r, b3;
                ldm_x4(a0, a1, a2, a3, aA2 + off);
                ldm_x4(b0, b1, b2r, b3, aC01 + off);
                mma16(acc2[0][0], acc2[0][1], acc2[0][2], acc2[0][3], a0, a1, a2, a3, b0, b1);
                mma16(acc2[1][0], acc2[1][1], acc2[1][2], acc2[1][3], a0, a1, a2, a3, b2r, b3);
            }
            #pragma unroll
            for (int nt = 0; nt < 2; nt++) {
                int n0 = 8 * (ntO2 + nt) + 2 * tig;
                float2 bb = *reinterpret_cast<const float2*>(b2_s + n0);
                float2 wd = *reinterpret_cast<const float2*>(Wd_s + n0);
                s0 += sigf(acc2[nt][0] + bb.x) * wd.x + sigf(acc2[nt][1] + bb.y) * wd.y;
                s1 += sigf(acc2[nt][2] + bb.x) * wd.x + sigf(acc2[nt][3] + bb.y) * wd.y;
            }
        }
        #pragma unroll
        for (int off = 1; off < 4; off <<= 1) {
            s0 += __shfl_xor_sync(0xffffffffu, s0, off);
            s1 += __shfl_xor_sync(0xffffffffu, s1, off);
        }
        // deferred combine: slot index == row index within chunk
        if (tig == 0) {
            float* p = part + ch * 128 + phalf + 16 * m + gid;
            p[0] = s0;
            p[8] = s1;
        }
        // no barrier: next staging only touches K_s (reads done before H1 barrier)
    }
    __syncthreads();   // part[] visible to all

    // ---- softmax over valid positions (scale 1/sqrt(64), bd cancels) ----
    float v = -INFINITY;
    if (tid < len) {
        const float* p = part + (tid >> 6) * 128 + (tid & 63);
        v = (p[0] + p[64]) * 0.125f;
    }
    float mx = v;
    #pragma unroll
    for (int s = 16; s; s >>= 1) mx = fmaxf(mx, __shfl_xor_sync(0xffffffffu, mx, s));
    if ((tid & 31) == 0) red[tid >> 5] = mx;
    __syncthreads();
    if (tid == 0) {
        float mm = red[0];
        #pragma unroll
        for (int i = 1; i < 8; i++) mm = fmaxf(mm, red[i]);
        red[0] = mm;
    }
    __syncthreads();
    const float M = red[0];

    float e = (tid < len) ? __expf(v - M) : 0.f;
    float s = e;
    #pragma unroll
    for (int o = 16; o; o >>= 1) s += __shfl_xor_sync(0xffffffffu, s, o);
    if ((tid & 31) == 0) red2[tid >> 5] = s;
    __syncthreads();
    if (tid == 0) {
        float ss = red2[0];
        #pragma unroll
        for (int i = 1; i < 8; i++) ss += red2[i];
        red2[0] = ss;
    }
    __syncthreads();
    const float inv_sum = 1.f / red2[0];
    if (tid < T_DIM) sc[tid] = e * inv_sum;
    __syncthreads();

    // ---- out[h] = sum_t att[t] * keys[b,t,h]  (fp32 keys) ----
    {
        const int g  = tid >> 6;   // 0..3
        const int hh = tid & 63;
        const float* pk = Kbase + g * H_DIM + hh;
        float acc = 0.f;
        int t = g;
        for (; t + 4 < len; t += 8) {
            acc += sc[t] * pk[0];
            acc += sc[t + 4] * pk[4 * H_DIM];
            pk += 8 * H_DIM;
        }
        if (t < len) acc += sc[t] * pk[0];
        obuf[tid] = acc;
        __syncthreads();
        if (tid < H_DIM)
            out[b * H_DIM + tid] =
                obuf[tid] + obuf[64 + tid] + obuf[128 + tid] + obuf[192 + tid];
    }
}

extern "C" void kernel_launch(void* const* d_in, const int* in_sizes, int n_in,
                              void* d_out, int out_size)
{
    const float* queries = (const float*)d_in[0];
    const float* keys    = (const float*)d_in[1];
    const int*   klen    = (const int*)d_in[2];
    const float* W1      = (const float*)d_in[3];
    const float* b1      = (const float*)d_in[4];
    const float* W2      = (const float*)d_in[5];
    const float* b2      = (const float*)d_in[6];
    const float* Wd      = (const float*)d_in[7];
    // d_in[8] = bd : uniform shift, cancels in softmax
    float* out = (float*)d_out;

    const int B = in_sizes[2];  // keys_length count
    const size_t smem = SMEM_FLOATS * sizeof(float);
    cudaFuncSetAttribute(seqatt_kernel,
                         cudaFuncAttributeMaxDynamicSharedMemorySize, (int)smem);
    seqatt_kernel<<<B, 256, smem>>>(queries, keys, klen, W1, b1, W2, b2, Wd, out);
}

// round 8
// speedup vs baseline: 4.0264x; 1.2181x over previous
#include <cuda_runtime.h>
#include <cuda_bf16.h>
#include <math.h>
#include <stdint.h>

// SequenceAttLayer: B=4096, T=200, H=64; MLP 256->80->40->1, masked softmax, att@keys.
// Algebra: x=[q,k,q-k,q*k];  x.W1 = k.(W1b-W1c + diag(q).W1d) + [q.(W1a+W1c)+b1]
// Round 8: bf16 mma + ldmatrix; fast sigmoid (ex2+rcp approx), parallel c-build,
// K-chunk register prefetch under layer2, normalize folded into output pass.

#define T_DIM 200
#define H_DIM 64
#define D1 80
#define D2 40

// strides in bf16 elements (row byte deltas 144/176 -> ldmatrix conflict-free)
#define K_STR   72   // K_s  [t][h]
#define H1_STR  88   // H1_s [t][j]
#define WT_STR  72   // W_t  [j][h]
#define W2T_STR 88   // W2_t [n][j]

// shared layout (float offsets; bf16 regions are 2x elements)
#define OFF_KS    0        // 64*72 bf16 = 2304 f
#define OFF_H1    2304     // 64*88 bf16 = 2816 f
#define OFF_WT    5120     // 80*72 bf16 = 2880 f
#define OFF_W2T   8000     // 40*88 bf16 = 1760 f
#define OFF_C     9760     // 160 (two halves, summed in epilogue)
#define OFF_B2    9920     // 40
#define OFF_WD    9960     // 40
#define OFF_Q     10000    // 64
#define OFF_PART  10064    // 4 chunks * 128 = 512
#define OFF_SC    10576    // 200 (unnormalized exp)
#define OFF_RED   10776    // 8
#define OFF_RED2  10784    // 8
#define OFF_OBUF  10792    // 256
#define SMEM_FLOATS 11048  // 44192 B -> 4 CTAs/SM

typedef __nv_bfloat16 bf16;

__device__ __forceinline__ uint32_t cvsm(const void* p) {
    return (uint32_t)__cvta_generic_to_shared(p);
}
__device__ __forceinline__ void ldm_x4(uint32_t& r0, uint32_t& r1,
                                       uint32_t& r2, uint32_t& r3, uint32_t a) {
    asm volatile("ldmatrix.sync.aligned.m8n8.x4.shared.b16 {%0,%1,%2,%3}, [%4];"
                 : "=r"(r0), "=r"(r1), "=r"(r2), "=r"(r3) : "r"(a));
}
__device__ __forceinline__ void ldm_x2(uint32_t& r0, uint32_t& r1, uint32_t a) {
    asm volatile("ldmatrix.sync.aligned.m8n8.x2.shared.b16 {%0,%1}, [%2];"
                 : "=r"(r0), "=r"(r1) : "r"(a));
}
__device__ __forceinline__ void mma16(float& d0, float& d1, float& d2, float& d3,
                                      uint32_t a0, uint32_t a1, uint32_t a2, uint32_t a3,
                                      uint32_t b0, uint32_t b1) {
    asm("mma.sync.aligned.m16n8k16.row.col.f32.bf16.bf16.f32 "
        "{%0,%1,%2,%3}, {%4,%5,%6,%7}, {%8,%9}, {%0,%1,%2,%3};"
        : "+f"(d0), "+f"(d1), "+f"(d2), "+f"(d3)
        : "r"(a0), "r"(a1), "r"(a2), "r"(a3), "r"(b0), "r"(b1));
}
__device__ __forceinline__ uint32_t pack_bf16(float lo, float hi) {
    uint32_t r;
    asm("cvt.rn.bf16x2.f32 %0, %1, %2;" : "=r"(r) : "f"(hi), "f"(lo));
    return r;
}
// sigmoid via ex2.approx + rcp.approx: FMUL + MUFU + FADD + MUFU
__device__ __forceinline__ float sigf(float z) {
    float e, r;
    asm("ex2.approx.f32 %0, %1;" : "=f"(e) : "f"(-1.4426950408889634f * z));
    asm("rcp.approx.f32 %0, %1;" : "=f"(r) : "f"(1.f + e));
    return r;
}

__global__ __launch_bounds__(256, 4)
void seqatt_kernel(const float* __restrict__ queries,
                   const float* __restrict__ keys,
                   const int* __restrict__ keys_length,
                   const float* __restrict__ W1,
                   const float* __restrict__ b1,
                   const float* __restrict__ W2,
                   const float* __restrict__ b2,
                   const float* __restrict__ Wd,
                   float* __restrict__ out)
{
    extern __shared__ float sm[];
    bf16* K_s   = reinterpret_cast<bf16*>(sm + OFF_KS);
    bf16* H1_s  = reinterpret_cast<bf16*>(sm + OFF_H1);
    bf16* W_t   = reinterpret_cast<bf16*>(sm + OFF_WT);
    bf16* W2_t  = reinterpret_cast<bf16*>(sm + OFF_W2T);
    float* c_s  = sm + OFF_C;
    float* b2_s = sm + OFF_B2;
    float* Wd_s = sm + OFF_WD;
    float* q_s  = sm + OFF_Q;
    float* part = sm + OFF_PART;
    float* sc   = sm + OFF_SC;
    float* red  = sm + OFF_RED;
    float* red2 = sm + OFF_RED2;
    float* obuf = sm + OFF_OBUF;

    const int b   = blockIdx.x;
    const int tid = threadIdx.x;
    // keys_length is int32 on device (JAX x64-disabled downcasts int64->int32).
    int len = keys_length[b];
    len = len < 1 ? 1 : (len > T_DIM ? T_DIM : len);

    // ---- phase 0: stage q, b2, Wd, W2_t; then build W_t (bf16) and c (fp32) ----
    if (tid < H_DIM) q_s[tid] = queries[b * H_DIM + tid];
    if (tid < D2) { b2_s[tid] = b2[tid]; Wd_s[tid] = Wd[tid]; }
    for (int i = tid; i < D1 * (D2 / 2); i += 256) {     // W2_t[n][j] = W2[j][n]
        int j = i / (D2 / 2), n2 = i - j * (D2 / 2);
        float2 v = *reinterpret_cast<const float2*>(W2 + j * D2 + 2 * n2);
        W2_t[(2 * n2)     * W2T_STR + j] = __float2bfloat16(v.x);
        W2_t[(2 * n2 + 1) * W2T_STR + j] = __float2bfloat16(v.y);
    }
    __syncthreads();

    // W_t[j][h] = W1b[h][j] - W1c[h][j] + q[h]*W1d[h][j]; float2 over j
    for (int i = tid; i < H_DIM * (D1 / 2); i += 256) {
        int h = i / (D1 / 2), j2 = i - h * (D1 / 2);
        float2 wb = *reinterpret_cast<const float2*>(W1 + (64  + h) * D1 + 2 * j2);
        float2 wc = *reinterpret_cast<const float2*>(W1 + (128 + h) * D1 + 2 * j2);
        float2 wd = *reinterpret_cast<const float2*>(W1 + (192 + h) * D1 + 2 * j2);
        float qh = q_s[h];
        W_t[(2 * j2)     * WT_STR + h] = __float2bfloat16(wb.x - wc.x + qh * wd.x);
        W_t[(2 * j2 + 1) * WT_STR + h] = __float2bfloat16(wb.y - wc.y + qh * wd.y);
    }
    // c halves: c_s[j] (h 0..31, +b1) and c_s[80+j] (h 32..63); summed in epilogue
    if (tid < 160) {
        int seg = (tid >= 80) ? 1 : 0;
        int j = tid - 80 * seg;
        float acc = seg ? 0.f : b1[j];
        const float* p1 = W1 + (32 * seg) * D1 + j;          // W1a
        const float* p2 = W1 + (128 + 32 * seg) * D1 + j;    // W1c
        const float* qq = q_s + 32 * seg;
        #pragma unroll 8
        for (int h = 0; h < 32; h++)
            acc += qq[h] * (p1[h * D1] + p2[h * D1]);
        c_s[seg * 80 + j] = acc;
    }

    const int w    = tid >> 5;
    const int lane = tid & 31;
    const int gid  = lane >> 2;
    const int tig  = lane & 3;
    const int m    = w & 3;           // m-tile: rows 16m..16m+15
    const int arow = 16 * m + gid;
    const int ntb0 = (w >> 2) * 5;    // layer1 n-tile base
    const int ntO2 = (w >> 2) * 3;    // layer2 n-tile base

    const int r8  = lane & 7;
    const int mi  = lane >> 3;
    const int mi2 = mi & 1;

    const uint32_t aA1 = cvsm(K_s)  + 2 * ((16 * m + r8 + ((mi & 1) << 3)) * K_STR  + ((mi >> 1) << 3));
    const uint32_t aA2 = cvsm(H1_s) + 2 * ((16 * m + r8 + ((mi & 1) << 3)) * H1_STR + ((mi >> 1) << 3));
    const uint32_t aB01 = cvsm(W_t) + 2 * ((8 * (ntb0 + (mi >> 1)) + r8) * WT_STR + ((mi & 1) << 3));
    const uint32_t aB23 = aB01 + 2 * (16 * WT_STR);
    const uint32_t aB4  = cvsm(W_t) + 2 * ((8 * (ntb0 + 4) + r8) * WT_STR + (mi2 << 3));
    const uint32_t aC01 = cvsm(W2_t) + 2 * ((8 * (ntO2 + (mi >> 1)) + r8) * W2T_STR + ((mi & 1) << 3));
    const uint32_t aC2  = cvsm(W2_t) + 2 * ((8 * (ntO2 + 2) + r8) * W2T_STR + (mi2 << 3));

    const float* Kbase = keys + (size_t)b * T_DIM * H_DIM;
    const int nchunk = (len + 63) >> 6;

    // staging geometry: row tid>>4 (+16/it), col 4*(tid&15)
    const int srow = tid >> 4;
    const int scol = (tid & 15) << 2;
    bf16* sdst0 = K_s + srow * K_STR + scol;
    const int phalf = (w >> 2) * 64;

    // ---- prologue: stage chunk 0 (rows 0..63, always in-bounds) ----
    {
        const float* g0 = Kbase + srow * H_DIM + scol;
        #pragma unroll
        for (int it = 0; it < 4; it++) {
            float4 f = *reinterpret_cast<const float4*>(g0 + it * (16 * H_DIM));
            uint2 u;
            u.x = pack_bf16(f.x, f.y);
            u.y = pack_bf16(f.z, f.w);
            *reinterpret_cast<uint2*>(sdst0 + it * (16 * K_STR)) = u;
        }
    }

    for (int ch = 0; ch < nchunk; ch++) {
        __syncthreads();   // A: K_s (and, at ch0, phase-0 W_t/c) ready

        // ---- layer 1: [64x80] = K @ W_eff + c, sigmoid -> H1_s (bf16) ----
        float acc1[5][4];
        #pragma unroll
        for (int nt = 0; nt < 5; nt++)
            #pragma unroll
            for (int i = 0; i < 4; i++) acc1[nt][i] = 0.f;

        #pragma unroll
        for (int ks = 0; ks < 4; ks++) {
            const uint32_t off = 32 * ks;
            uint32_t a0, a1, a2, a3;
            ldm_x4(a0, a1, a2, a3, aA1 + off);
            uint32_t b0, b1r, b2r, b3, b4, b5;
            ldm_x4(b0, b1r, b2r, b3, aB01 + off);
            mma16(acc1[0][0], acc1[0][1], acc1[0][2], acc1[0][3], a0, a1, a2, a3, b0, b1r);
            mma16(acc1[1][0], acc1[1][1], acc1[1][2], acc1[1][3], a0, a1, a2, a3, b2r, b3);
            ldm_x4(b0, b1r, b2r, b3, aB23 + off);
            mma16(acc1[2][0], acc1[2][1], acc1[2][2], acc1[2][3], a0, a1, a2, a3, b0, b1r);
            mma16(acc1[3][0], acc1[3][1], acc1[3][2], acc1[3][3], a0, a1, a2, a3, b2r, b3);
            ldm_x2(b4, b5, aB4 + off);
            mma16(acc1[4][0], acc1[4][1], acc1[4][2], acc1[4][3], a0, a1, a2, a3, b4, b5);
        }
        #pragma unroll
        for (int nt = 0; nt < 5; nt++) {
            int n0 = 8 * (ntb0 + nt) + 2 * tig;
            float2 cA = *reinterpret_cast<const float2*>(c_s + n0);
            float2 cB = *reinterpret_cast<const float2*>(c_s + 80 + n0);
            float ccx = cA.x + cB.x, ccy = cA.y + cB.y;
            uint32_t lo = pack_bf16(sigf(acc1[nt][0] + ccx), sigf(acc1[nt][1] + ccy));
            uint32_t hi = pack_bf16(sigf(acc1[nt][2] + ccx), sigf(acc1[nt][3] + ccy));
            *reinterpret_cast<uint32_t*>(H1_s + arow * H1_STR + n0) = lo;
            *reinterpret_cast<uint32_t*>(H1_s + (arow + 8) * H1_STR + n0) = hi;
        }
        __syncthreads();   // B: H1 ready; all K_s reads done

        // ---- prefetch next K chunk into registers (latency hidden by layer2) ----
        const bool has_next = (ch + 1) < nchunk;
        float4 pf0, pf1, pf2, pf3;
        if (has_next) {
            const int t0n = (ch + 1) << 6;
            if (t0n + 64 <= T_DIM) {
                const float* g0 = Kbase + (t0n + srow) * H_DIM + scol;
                pf0 = *reinterpret_cast<const float4*>(g0);
                pf1 = *reinterpret_cast<const float4*>(g0 + 16 * H_DIM);
                pf2 = *reinterpret_cast<const float4*>(g0 + 32 * H_DIM);
                pf3 = *reinterpret_cast<const float4*>(g0 + 48 * H_DIM);
            } else {
                int r0 = t0n + srow;
                int r1 = r0 + 16, r2 = r0 + 32, r3 = r0 + 48;
                r0 = r0 < T_DIM ? r0 : T_DIM - 1;
                r1 = r1 < T_DIM ? r1 : T_DIM - 1;
                r2 = r2 < T_DIM ? r2 : T_DIM - 1;
                r3 = r3 < T_DIM ? r3 : T_DIM - 1;
                pf0 = *reinterpret_cast<const float4*>(Kbase + r0 * H_DIM + scol);
                pf1 = *reinterpret_cast<const float4*>(Kbase + r1 * H_DIM + scol);
                pf2 = *reinterpret_cast<const float4*>(Kbase + r2 * H_DIM + scol);
                pf3 = *reinterpret_cast<const float4*>(Kbase + r3 * H_DIM + scol);
            }
        }

        // ---- layer 2 + head: [64x40] = H1 @ W2, sigmoid, dot Wd ----
        float s0 = 0.f, s1 = 0.f;
        if (w < 4) {
            float acc2[3][4];
            #pragma unroll
            for (int nt = 0; nt < 3; nt++)
                #pragma unroll
                for (int i = 0; i < 4; i++) acc2[nt][i] = 0.f;
            #pragma unroll
            for (int ks = 0; ks < 5; ks++) {
                const uint32_t off = 32 * ks;
                uint32_t a0, a1, a2, a3, b0, b1r, b2r, b3;
                ldm_x4(a0, a1, a2, a3, aA2 + off);
                ldm_x4(b0, b1r, b2r, b3, aC01 + off);
                mma16(acc2[0][0], acc2[0][1], acc2[0][2], acc2[0][3], a0, a1, a2, a3, b0, b1r);
                mma16(acc2[1][0], acc2[1][1], acc2[1][2], acc2[1][3], a0, a1, a2, a3, b2r, b3);
                ldm_x2(b0, b1r, aC2 + off);
                mma16(acc2[2][0], acc2[2][1], acc2[2][2], acc2[2][3], a0, a1, a2, a3, b0, b1r);
            }
            #pragma unroll
            for (int nt = 0; nt < 3; nt++) {
                int n0 = 8 * (ntO2 + nt) + 2 * tig;
                float2 bb = *reinterpret_cast<const float2*>(b2_s + n0);
                float2 wd = *reinterpret_cast<const float2*>(Wd_s + n0);
                s0 += sigf(acc2[nt][0] + bb.x) * wd.x + sigf(acc2[nt][1] + bb.y) * wd.y;
                s1 += sigf(acc2[nt][2] + bb.x) * wd.x + sigf(acc2[nt][3] + bb.y) * wd.y;
            }
        } else {
            float acc2[2][4];
            #pragma unroll
            for (int nt = 0; nt < 2; nt++)
                #pragma unroll
                for (int i = 0; i < 4; i++) acc2[nt][i] = 0.f;
            #pragma unroll
            for (int ks = 0; ks < 5; ks++) {
                const uint32_t off = 32 * ks;
                uint32_t a0, a1, a2, a3, b0, b1r, b2r, b3;
                ldm_x4(a0, a1, a2, a3, aA2 + off);
                ldm_x4(b0, b1r, b2r, b3, aC01 + off);
                mma16(acc2[0][0], acc2[0][1], acc2[0][2], acc2[0][3], a0, a1, a2, a3, b0, b1r);
                mma16(acc2[1][0], acc2[1][1], acc2[1][2], acc2[1][3], a0, a1, a2, a3, b2r, b3);
            }
            #pragma unroll
            for (int nt = 0; nt < 2; nt++) {
                int n0 = 8 * (ntO2 + nt) + 2 * tig;
                float2 bb = *reinterpret_cast<const float2*>(b2_s + n0);
                float2 wd = *reinterpret_cast<const float2*>(Wd_s + n0);
                s0 += sigf(acc2[nt][0] + bb.x) * wd.x + sigf(acc2[nt][1] + bb.y) * wd.y;
                s1 += sigf(acc2[nt][2] + bb.x) * wd.x + sigf(acc2[nt][3] + bb.y) * wd.y;
            }
        }
        #pragma unroll
        for (int off = 1; off < 4; off <<= 1) {
            s0 += __shfl_xor_sync(0xffffffffu, s0, off);
            s1 += __shfl_xor_sync(0xffffffffu, s1, off);
        }
        if (tig == 0) {
            float* p = part + ch * 128 + phalf + 16 * m + gid;
            p[0] = s0;
            p[8] = s1;
        }

        // ---- store prefetched K (reads done at barrier B; visible after next A) ----
        if (has_next) {
            uint2 u;
            u.x = pack_bf16(pf0.x, pf0.y); u.y = pack_bf16(pf0.z, pf0.w);
            *reinterpret_cast<uint2*>(sdst0) = u;
            u.x = pack_bf16(pf1.x, pf1.y); u.y = pack_bf16(pf1.z, pf1.w);
            *reinterpret_cast<uint2*>(sdst0 + 16 * K_STR) = u;
            u.x = pack_bf16(pf2.x, pf2.y); u.y = pack_bf16(pf2.z, pf2.w);
            *reinterpret_cast<uint2*>(sdst0 + 32 * K_STR) = u;
            u.x = pack_bf16(pf3.x, pf3.y); u.y = pack_bf16(pf3.z, pf3.w);
            *reinterpret_cast<uint2*>(sdst0 + 48 * K_STR) = u;
        }
    }
    __syncthreads();   // part[] visible

    // ---- softmax over valid positions (scale 1/sqrt(64), bd cancels) ----
    float v = -INFINITY;
    if (tid < len) {
        const float* p = part + (tid >> 6) * 128 + (tid & 63);
        v = (p[0] + p[64]) * 0.125f;
    }
    float mx = v;
    #pragma unroll
    for (int s = 16; s; s >>= 1) mx = fmaxf(mx, __shfl_xor_sync(0xffffffffu, mx, s));
    if ((tid & 31) == 0) red[tid >> 5] = mx;
    __syncthreads();
    if (tid == 0) {
        float mm = red[0];
        #pragma unroll
        for (int i = 1; i < 8; i++) mm = fmaxf(mm, red[i]);
        red[0] = mm;
    }
    __syncthreads();
    const float M = red[0];

    float e = (tid < len) ? __expf(v - M) : 0.f;
    if (tid < T_DIM) sc[tid] = e;      // unnormalized; normalize in output pass
    float s = e;
    #pragma unroll
    for (int o = 16; o; o >>= 1) s += __shfl_xor_sync(0xffffffffu, s, o);
    if ((tid & 31) == 0) red2[tid >> 5] = s;
    __syncthreads();                    // also makes sc[] visible
    if (tid == 0) {
        float ss = red2[0];
        #pragma unroll
        for (int i = 1; i < 8; i++) ss += red2[i];
        red2[0] = ss;
    }
    __syncthreads();
    const float inv_sum = 1.f / red2[0];

    // ---- out[h] = inv_sum * sum_t e[t] * keys[b,t,h] ----
    {
        const int g  = tid >> 6;   // 0..3
        const int hh = tid & 63;
        const float* pk = Kbase + g * H_DIM + hh;
        float acc = 0.f;
        int t = g;
        for (; t + 4 < len; t += 8) {
            acc += sc[t] * pk[0];
            acc += sc[t + 4] * pk[4 * H_DIM];
            pk += 8 * H_DIM;
        }
        if (t < len) acc += sc[t] * pk[0];
        obuf[tid] = acc;
        __syncthreads();
        if (tid < H_DIM)
            out[b * H_DIM + tid] = inv_sum *
                (obuf[tid] + obuf[64 + tid] + obuf[128 + tid] + obuf[192 + tid]);
    }
}

extern "C" void kernel_launch(void* const* d_in, const int* in_sizes, int n_in,
                              void* d_out, int out_size)
{
    const float* queries = (const float*)d_in[0];
    const float* keys    = (const float*)d_in[1];
    const int*   klen    = (const int*)d_in[2];
    const float* W1      = (const float*)d_in[3];
    const float* b1      = (const float*)d_in[4];
    const float* W2      = (const float*)d_in[5];
    const float* b2      = (const float*)d_in[6];
    const float* Wd      = (const float*)d_in[7];
    // d_in[8] = bd : uniform shift, cancels in softmax
    float* out = (float*)d_out;

    const int B = in_sizes[2];  // keys_length count
    const size_t smem = SMEM_FLOATS * sizeof(float);
    cudaFuncSetAttribute(seqatt_kernel,
                         cudaFuncAttributeMaxDynamicSharedMemorySize, (int)smem);
    seqatt_kernel<<<B, 256, smem>>>(queries, keys, klen, W1, b1, W2, b2, Wd, out);
}

// round 9
// speedup vs baseline: 4.0955x; 1.0172x over previous
#include <cuda_runtime.h>
#include <cuda_bf16.h>
#include <math.h>
#include <stdint.h>

// SequenceAttLayer: B=4096, T=200, H=64; MLP 256->80->40->1, masked softmax, att@keys.
// Algebra: x=[q,k,q-k,q*k];  x.W1 = k.(W1b-W1c + diag(q).W1d) + [q.(W1a+W1c)+b1]
// Round 9: float4 output pass (16x16 tiling), 2-barrier softmax with per-thread
// final folds, ex2.approx exp. MMA/staging/prefetch unchanged from round 8.

#define T_DIM 200
#define H_DIM 64
#define D1 80
#define D2 40

#define K_STR   72
#define H1_STR  88
#define WT_STR  72
#define W2T_STR 88

// shared layout (float offsets; bf16 regions are 2x elements)
#define OFF_KS    0        // 64*72 bf16 = 2304 f
#define OFF_H1    2304     // 64*88 bf16 = 2816 f
#define OFF_WT    5120     // 80*72 bf16 = 2880 f
#define OFF_W2T   8000     // 40*88 bf16 = 1760 f
#define OFF_C     9760     // 160 (two halves)
#define OFF_B2    9920     // 40
#define OFF_WD    9960     // 40
#define OFF_Q     10000    // 64
#define OFF_PART  10064    // 4 chunks * 128 = 512
#define OFF_SC    10576    // 200 (unnormalized exp)
#define OFF_RED   10776    // 8
#define OFF_RED2  10784    // 8
#define OFF_OBUF  10792    // 16*64 = 1024
#define SMEM_FLOATS 11816  // 47264 B -> 4 CTAs/SM

typedef __nv_bfloat16 bf16;

__device__ __forceinline__ uint32_t cvsm(const void* p) {
    return (uint32_t)__cvta_generic_to_shared(p);
}
__device__ __forceinline__ void ldm_x4(uint32_t& r0, uint32_t& r1,
                                       uint32_t& r2, uint32_t& r3, uint32_t a) {
    asm volatile("ldmatrix.sync.aligned.m8n8.x4.shared.b16 {%0,%1,%2,%3}, [%4];"
                 : "=r"(r0), "=r"(r1), "=r"(r2), "=r"(r3) : "r"(a));
}
__device__ __forceinline__ void ldm_x2(uint32_t& r0, uint32_t& r1, uint32_t a) {
    asm volatile("ldmatrix.sync.aligned.m8n8.x2.shared.b16 {%0,%1}, [%2];"
                 : "=r"(r0), "=r"(r1) : "r"(a));
}
__device__ __forceinline__ void mma16(float& d0, float& d1, float& d2, float& d3,
                                      uint32_t a0, uint32_t a1, uint32_t a2, uint32_t a3,
                                      uint32_t b0, uint32_t b1) {
    asm("mma.sync.aligned.m16n8k16.row.col.f32.bf16.bf16.f32 "
        "{%0,%1,%2,%3}, {%4,%5,%6,%7}, {%8,%9}, {%0,%1,%2,%3};"
        : "+f"(d0), "+f"(d1), "+f"(d2), "+f"(d3)
        : "r"(a0), "r"(a1), "r"(a2), "r"(a3), "r"(b0), "r"(b1));
}
__device__ __forceinline__ uint32_t pack_bf16(float lo, float hi) {
    uint32_t r;
    asm("cvt.rn.bf16x2.f32 %0, %1, %2;" : "=r"(r) : "f"(hi), "f"(lo));
    return r;
}
__device__ __forceinline__ float ex2f(float x) {
    float r;
    asm("ex2.approx.f32 %0, %1;" : "=f"(r) : "f"(x));
    return r;
}
__device__ __forceinline__ float sigf(float z) {
    float e = ex2f(-1.4426950408889634f * z);
    float r;
    asm("rcp.approx.f32 %0, %1;" : "=f"(r) : "f"(1.f + e));
    return r;
}

__global__ __launch_bounds__(256, 4)
void seqatt_kernel(const float* __restrict__ queries,
                   const float* __restrict__ keys,
                   const int* __restrict__ keys_length,
                   const float* __restrict__ W1,
                   const float* __restrict__ b1,
                   const float* __restrict__ W2,
                   const float* __restrict__ b2,
                   const float* __restrict__ Wd,
                   float* __restrict__ out)
{
    extern __shared__ float sm[];
    bf16* K_s   = reinterpret_cast<bf16*>(sm + OFF_KS);
    bf16* H1_s  = reinterpret_cast<bf16*>(sm + OFF_H1);
    bf16* W_t   = reinterpret_cast<bf16*>(sm + OFF_WT);
    bf16* W2_t  = reinterpret_cast<bf16*>(sm + OFF_W2T);
    float* c_s  = sm + OFF_C;
    float* b2_s = sm + OFF_B2;
    float* Wd_s = sm + OFF_WD;
    float* q_s  = sm + OFF_Q;
    float* part = sm + OFF_PART;
    float* sc   = sm + OFF_SC;
    float* red  = sm + OFF_RED;
    float* red2 = sm + OFF_RED2;
    float* obuf = sm + OFF_OBUF;

    const int b   = blockIdx.x;
    const int tid = threadIdx.x;
    // keys_length is int32 on device (JAX x64-disabled downcasts int64->int32).
    int len = keys_length[b];
    len = len < 1 ? 1 : (len > T_DIM ? T_DIM : len);

    // ---- phase 0 ----
    if (tid < H_DIM) q_s[tid] = queries[b * H_DIM + tid];
    if (tid < D2) { b2_s[tid] = b2[tid]; Wd_s[tid] = Wd[tid]; }
    for (int i = tid; i < D1 * (D2 / 2); i += 256) {     // W2_t[n][j] = W2[j][n]
        int j = i / (D2 / 2), n2 = i - j * (D2 / 2);
        float2 v = *reinterpret_cast<const float2*>(W2 + j * D2 + 2 * n2);
        W2_t[(2 * n2)     * W2T_STR + j] = __float2bfloat16(v.x);
        W2_t[(2 * n2 + 1) * W2T_STR + j] = __float2bfloat16(v.y);
    }
    __syncthreads();

    for (int i = tid; i < H_DIM * (D1 / 2); i += 256) {  // W_t[j][h]
        int h = i / (D1 / 2), j2 = i - h * (D1 / 2);
        float2 wb = *reinterpret_cast<const float2*>(W1 + (64  + h) * D1 + 2 * j2);
        float2 wc = *reinterpret_cast<const float2*>(W1 + (128 + h) * D1 + 2 * j2);
        float2 wd = *reinterpret_cast<const float2*>(W1 + (192 + h) * D1 + 2 * j2);
        float qh = q_s[h];
        W_t[(2 * j2)     * WT_STR + h] = __float2bfloat16(wb.x - wc.x + qh * wd.x);
        W_t[(2 * j2 + 1) * WT_STR + h] = __float2bfloat16(wb.y - wc.y + qh * wd.y);
    }
    if (tid < 160) {   // c halves, summed in the layer-1 epilogue
        int seg = (tid >= 80) ? 1 : 0;
        int j = tid - 80 * seg;
        float acc = seg ? 0.f : b1[j];
        const float* p1 = W1 + (32 * seg) * D1 + j;
        const float* p2 = W1 + (128 + 32 * seg) * D1 + j;
        const float* qq = q_s + 32 * seg;
        #pragma unroll 8
        for (int h = 0; h < 32; h++)
            acc += qq[h] * (p1[h * D1] + p2[h * D1]);
        c_s[seg * 80 + j] = acc;
    }

    const int w    = tid >> 5;
    const int lane = tid & 31;
    const int gid  = lane >> 2;
    const int tig  = lane & 3;
    const int m    = w & 3;
    const int arow = 16 * m + gid;
    const int ntb0 = (w >> 2) * 5;
    const int ntO2 = (w >> 2) * 3;

    const int r8  = lane & 7;
    const int mi  = lane >> 3;
    const int mi2 = mi & 1;

    const uint32_t aA1 = cvsm(K_s)  + 2 * ((16 * m + r8 + ((mi & 1) << 3)) * K_STR  + ((mi >> 1) << 3));
    const uint32_t aA2 = cvsm(H1_s) + 2 * ((16 * m + r8 + ((mi & 1) << 3)) * H1_STR + ((mi >> 1) << 3));
    const uint32_t aB01 = cvsm(W_t) + 2 * ((8 * (ntb0 + (mi >> 1)) + r8) * WT_STR + ((mi & 1) << 3));
    const uint32_t aB23 = aB01 + 2 * (16 * WT_STR);
    const uint32_t aB4  = cvsm(W_t) + 2 * ((8 * (ntb0 + 4) + r8) * WT_STR + (mi2 << 3));
    const uint32_t aC01 = cvsm(W2_t) + 2 * ((8 * (ntO2 + (mi >> 1)) + r8) * W2T_STR + ((mi & 1) << 3));
    const uint32_t aC2  = cvsm(W2_t) + 2 * ((8 * (ntO2 + 2) + r8) * W2T_STR + (mi2 << 3));

    const float* Kbase = keys + (size_t)b * T_DIM * H_DIM;
    const int nchunk = (len + 63) >> 6;

    const int srow = tid >> 4;
    const int scol = (tid & 15) << 2;
    bf16* sdst0 = K_s + srow * K_STR + scol;
    const int phalf = (w >> 2) * 64;

    // ---- prologue: stage chunk 0 ----
    {
        const float* g0 = Kbase + srow * H_DIM + scol;
        #pragma unroll
        for (int it = 0; it < 4; it++) {
            float4 f = *reinterpret_cast<const float4*>(g0 + it * (16 * H_DIM));
            uint2 u;
            u.x = pack_bf16(f.x, f.y);
            u.y = pack_bf16(f.z, f.w);
            *reinterpret_cast<uint2*>(sdst0 + it * (16 * K_STR)) = u;
        }
    }

    for (int ch = 0; ch < nchunk; ch++) {
        __syncthreads();   // A: K_s (and at ch0, W_t/c) ready

        // ---- layer 1 ----
        float acc1[5][4];
        #pragma unroll
        for (int nt = 0; nt < 5; nt++)
            #pragma unroll
            for (int i = 0; i < 4; i++) acc1[nt][i] = 0.f;

        #pragma unroll
        for (int ks = 0; ks < 4; ks++) {
            const uint32_t off = 32 * ks;
            uint32_t a0, a1, a2, a3;
            ldm_x4(a0, a1, a2, a3, aA1 + off);
            uint32_t b0, b1r, b2r, b3, b4, b5;
            ldm_x4(b0, b1r, b2r, b3, aB01 + off);
            mma16(acc1[0][0], acc1[0][1], acc1[0][2], acc1[0][3], a0, a1, a2, a3, b0, b1r);
            mma16(acc1[1][0], acc1[1][1], acc1[1][2], acc1[1][3], a0, a1, a2, a3, b2r, b3);
            ldm_x4(b0, b1r, b2r, b3, aB23 + off);
            mma16(acc1[2][0], acc1[2][1], acc1[2][2], acc1[2][3], a0, a1, a2, a3, b0, b1r);
            mma16(acc1[3][0], acc1[3][1], acc1[3][2], acc1[3][3], a0, a1, a2, a3, b2r, b3);
            ldm_x2(b4, b5, aB4 + off);
            mma16(acc1[4][0], acc1[4][1], acc1[4][2], acc1[4][3], a0, a1, a2, a3, b4, b5);
        }
        #pragma unroll
        for (int nt = 0; nt < 5; nt++) {
            int n0 = 8 * (ntb0 + nt) + 2 * tig;
            float2 cA = *reinterpret_cast<const float2*>(c_s + n0);
            float2 cB = *reinterpret_cast<const float2*>(c_s + 80 + n0);
            float ccx = cA.x + cB.x, ccy = cA.y + cB.y;
            uint32_t lo = pack_bf16(sigf(acc1[nt][0] + ccx), sigf(acc1[nt][1] + ccy));
            uint32_t hi = pack_bf16(sigf(acc1[nt][2] + ccx), sigf(acc1[nt][3] + ccy));
            *reinterpret_cast<uint32_t*>(H1_s + arow * H1_STR + n0) = lo;
            *reinterpret_cast<uint32_t*>(H1_s + (arow + 8) * H1_STR + n0) = hi;
        }
        __syncthreads();   // B: H1 ready; all K_s reads done

        // ---- prefetch next K chunk into registers ----
        const bool has_next = (ch + 1) < nchunk;
        float4 pf0, pf1, pf2, pf3;
        if (has_next) {
            const int t0n = (ch + 1) << 6;
            if (t0n + 64 <= T_DIM) {
                const float* g0 = Kbase + (t0n + srow) * H_DIM + scol;
                pf0 = *reinterpret_cast<const float4*>(g0);
                pf1 = *reinterpret_cast<const float4*>(g0 + 16 * H_DIM);
                pf2 = *reinterpret_cast<const float4*>(g0 + 32 * H_DIM);
                pf3 = *reinterpret_cast<const float4*>(g0 + 48 * H_DIM);
            } else {
                int r0 = t0n + srow;
                int r1 = r0 + 16, r2 = r0 + 32, r3 = r0 + 48;
                r0 = r0 < T_DIM ? r0 : T_DIM - 1;
                r1 = r1 < T_DIM ? r1 : T_DIM - 1;
                r2 = r2 < T_DIM ? r2 : T_DIM - 1;
                r3 = r3 < T_DIM ? r3 : T_DIM - 1;
                pf0 = *reinterpret_cast<const float4*>(Kbase + r0 * H_DIM + scol);
                pf1 = *reinterpret_cast<const float4*>(Kbase + r1 * H_DIM + scol);
                pf2 = *reinterpret_cast<const float4*>(Kbase + r2 * H_DIM + scol);
                pf3 = *reinterpret_cast<const float4*>(Kbase + r3 * H_DIM + scol);
            }
        }

        // ---- layer 2 + head ----
        float s0 = 0.f, s1 = 0.f;
        if (w < 4) {
            float acc2[3][4];
            #pragma unroll
            for (int nt = 0; nt < 3; nt++)
                #pragma unroll
                for (int i = 0; i < 4; i++) acc2[nt][i] = 0.f;
            #pragma unroll
            for (int ks = 0; ks < 5; ks++) {
                const uint32_t off = 32 * ks;
                uint32_t a0, a1, a2, a3, b0, b1r, b2r, b3;
                ldm_x4(a0, a1, a2, a3, aA2 + off);
                ldm_x4(b0, b1r, b2r, b3, aC01 + off);
                mma16(acc2[0][0], acc2[0][1], acc2[0][2], acc2[0][3], a0, a1, a2, a3, b0, b1r);
                mma16(acc2[1][0], acc2[1][1], acc2[1][2], acc2[1][3], a0, a1, a2, a3, b2r, b3);
                ldm_x2(b0, b1r, aC2 + off);
                mma16(acc2[2][0], acc2[2][1], acc2[2][2], acc2[2][3], a0, a1, a2, a3, b0, b1r);
            }
            #pragma unroll
            for (int nt = 0; nt < 3; nt++) {
                int n0 = 8 * (ntO2 + nt) + 2 * tig;
                float2 bb = *reinterpret_cast<const float2*>(b2_s + n0);
                float2 wd = *reinterpret_cast<const float2*>(Wd_s + n0);
                s0 += sigf(acc2[nt][0] + bb.x) * wd.x + sigf(acc2[nt][1] + bb.y) * wd.y;
                s1 += sigf(acc2[nt][2] + bb.x) * wd.x + sigf(acc2[nt][3] + bb.y) * wd.y;
            }
        } else {
            float acc2[2][4];
            #pragma unroll
            for (int nt = 0; nt < 2; nt++)
                #pragma unroll
                for (int i = 0; i < 4; i++) acc2[nt][i] = 0.f;
            #pragma unroll
            for (int ks = 0; ks < 5; ks++) {
                const uint32_t off = 32 * ks;
                uint32_t a0, a1, a2, a3, b0, b1r, b2r, b3;
                ldm_x4(a0, a1, a2, a3, aA2 + off);
                ldm_x4(b0, b1r, b2r, b3, aC01 + off);
                mma16(acc2[0][0], acc2[0][1], acc2[0][2], acc2[0][3], a0, a1, a2, a3, b0, b1r);
                mma16(acc2[1][0], acc2[1][1], acc2[1][2], acc2[1][3], a0, a1, a2, a3, b2r, b3);
            }
            #pragma unroll
            for (int nt = 0; nt < 2; nt++) {
                int n0 = 8 * (ntO2 + nt) + 2 * tig;
                float2 bb = *reinterpret_cast<const float2*>(b2_s + n0);
                float2 wd = *reinterpret_cast<const float2*>(Wd_s + n0);
                s0 += sigf(acc2[nt][0] + bb.x) * wd.x + sigf(acc2[nt][1] + bb.y) * wd.y;
                s1 += sigf(acc2[nt][2] + bb.x) * wd.x + sigf(acc2[nt][3] + bb.y) * wd.y;
            }
        }
        #pragma unroll
        for (int off = 1; off < 4; off <<= 1) {
            s0 += __shfl_xor_sync(0xffffffffu, s0, off);
            s1 += __shfl_xor_sync(0xffffffffu, s1, off);
        }
        if (tig == 0) {
            float* p = part + ch * 128 + phalf + 16 * m + gid;
            p[0] = s0;
            p[8] = s1;
        }

        if (has_next) {
            uint2 u;
            u.x = pack_bf16(pf0.x, pf0.y); u.y = pack_bf16(pf0.z, pf0.w);
            *reinterpret_cast<uint2*>(sdst0) = u;
            u.x = pack_bf16(pf1.x, pf1.y); u.y = pack_bf16(pf1.z, pf1.w);
            *reinterpret_cast<uint2*>(sdst0 + 16 * K_STR) = u;
            u.x = pack_bf16(pf2.x, pf2.y); u.y = pack_bf16(pf2.z, pf2.w);
            *reinterpret_cast<uint2*>(sdst0 + 32 * K_STR) = u;
            u.x = pack_bf16(pf3.x, pf3.y); u.y = pack_bf16(pf3.z, pf3.w);
            *reinterpret_cast<uint2*>(sdst0 + 48 * K_STR) = u;
        }
    }
    __syncthreads();   // part[] visible

    // ---- softmax (2 barriers): scale 1/sqrt(64); bd cancels ----
    float v = -INFINITY;
    if (tid < len) {
        const float* p = part + (tid >> 6) * 128 + (tid & 63);
        v = (p[0] + p[64]) * 0.125f;
    }
    float mx = v;
    #pragma unroll
    for (int s = 16; s; s >>= 1) mx = fmaxf(mx, __shfl_xor_sync(0xffffffffu, mx, s));
    if (lane == 0) red[w] = mx;
    __syncthreads();
    float M = red[0];
    #pragma unroll
    for (int i = 1; i < 8; i++) M = fmaxf(M, red[i]);

    float e = (tid < len) ? ex2f(1.4426950408889634f * (v - M)) : 0.f;
    if (tid < T_DIM) sc[tid] = e;       // unnormalized
    float s = e;
    #pragma unroll
    for (int o = 16; o; o >>= 1) s += __shfl_xor_sync(0xffffffffu, s, o);
    if (lane == 0) red2[w] = s;
    __syncthreads();                     // sc[] + red2[] visible
    float ssum = red2[0];
    #pragma unroll
    for (int i = 1; i < 8; i++) ssum += red2[i];
    const float inv_sum = 1.f / ssum;

    // ---- out[h] = inv_sum * sum_t e[t]*keys[b,t,h]; float4, 16 t-groups ----
    {
        const int g  = tid >> 4;            // 0..15 t-group
        const int c4 = (tid & 15) << 2;     // h base
        const float* pk = Kbase + g * H_DIM + c4;
        float4 acc = make_float4(0.f, 0.f, 0.f, 0.f);
        for (int t = g; t < len; t += 16) {
            float wt = sc[t];
            float4 k4 = *reinterpret_cast<const float4*>(pk);
            acc.x += wt * k4.x; acc.y += wt * k4.y;
            acc.z += wt * k4.z; acc.w += wt * k4.w;
            pk += 16 * H_DIM;
        }
        *reinterpret_cast<float4*>(obuf + g * 64 + c4) = acc;
        __syncthreads();
        if (tid < H_DIM) {
            float o = 0.f;
            #pragma unroll
            for (int i = 0; i < 16; i++) o += obuf[i * 64 + tid];
            out[b * H_DIM + tid] = inv_sum * o;
        }
    }
}

extern "C" void kernel_launch(void* const* d_in, const int* in_sizes, int n_in,
                              void* d_out, int out_size)
{
    const float* queries = (const float*)d_in[0];
    const float* keys    = (const float*)d_in[1];
    const int*   klen    = (const int*)d_in[2];
    const float* W1      = (const float*)d_in[3];
    const float* b1      = (const float*)d_in[4];
    const float* W2      = (const float*)d_in[5];
    const float* b2      = (const float*)d_in[6];
    const float* Wd      = (const float*)d_in[7];
    // d_in[8] = bd : uniform shift, cancels in softmax
    float* out = (float*)d_out;

    const int B = in_sizes[2];  // keys_length count
    const size_t smem = SMEM_FLOATS * sizeof(float);
    cudaFuncSetAttribute(seqatt_kernel,
                         cudaFuncAttributeMaxDynamicSharedMemorySize, (int)smem);
    seqatt_kernel<<<B, 256, smem>>>(queries, keys, klen, W1, b1, W2, b2, Wd, out);
}

// round 10
// speedup vs baseline: 4.2720x; 1.0431x over previous
#include <cuda_runtime.h>
#include <cuda_bf16.h>
#include <math.h>
#include <stdint.h>

// SequenceAttLayer: B=4096, T=200, H=64; MLP 256->80->40->1, masked softmax, att@keys.
// Algebra: x=[q,k,q-k,q*k];  x.W1 = k.(W1b-W1c + diag(q).W1d) + [q.(W1a+W1c)+b1]
// Round 10: warp-level tail-tile skip (m-tiles fully past len do no GEMM work),
// on top of round 9 (bf16 mma + ldmatrix, prefetch, 2-barrier softmax, f4 output).

#define T_DIM 200
#define H_DIM 64
#define D1 80
#define D2 40

#define K_STR   72
#define H1_STR  88
#define WT_STR  72
#define W2T_STR 88

// shared layout (float offsets; bf16 regions are 2x elements)
#define OFF_KS    0        // 64*72 bf16 = 2304 f
#define OFF_H1    2304     // 64*88 bf16 = 2816 f
#define OFF_WT    5120     // 80*72 bf16 = 2880 f
#define OFF_W2T   8000     // 40*88 bf16 = 1760 f
#define OFF_C     9760     // 160 (two halves)
#define OFF_B2    9920     // 40
#define OFF_WD    9960     // 40
#define OFF_Q     10000    // 64
#define OFF_PART  10064    // 4 chunks * 128 = 512
#define OFF_SC    10576    // 200 (unnormalized exp)
#define OFF_RED   10776    // 8
#define OFF_RED2  10784    // 8
#define OFF_OBUF  10792    // 16*64 = 1024
#define SMEM_FLOATS 11816  // 47264 B -> 4 CTAs/SM

typedef __nv_bfloat16 bf16;

__device__ __forceinline__ uint32_t cvsm(const void* p) {
    return (uint32_t)__cvta_generic_to_shared(p);
}
__device__ __forceinline__ void ldm_x4(uint32_t& r0, uint32_t& r1,
                                       uint32_t& r2, uint32_t& r3, uint32_t a) {
    asm volatile("ldmatrix.sync.aligned.m8n8.x4.shared.b16 {%0,%1,%2,%3}, [%4];"
                 : "=r"(r0), "=r"(r1), "=r"(r2), "=r"(r3) : "r"(a));
}
__device__ __forceinline__ void ldm_x2(uint32_t& r0, uint32_t& r1, uint32_t a) {
    asm volatile("ldmatrix.sync.aligned.m8n8.x2.shared.b16 {%0,%1}, [%2];"
                 : "=r"(r0), "=r"(r1) : "r"(a));
}
__device__ __forceinline__ void mma16(float& d0, float& d1, float& d2, float& d3,
                                      uint32_t a0, uint32_t a1, uint32_t a2, uint32_t a3,
                                      uint32_t b0, uint32_t b1) {
    asm("mma.sync.aligned.m16n8k16.row.col.f32.bf16.bf16.f32 "
        "{%0,%1,%2,%3}, {%4,%5,%6,%7}, {%8,%9}, {%0,%1,%2,%3};"
        : "+f"(d0), "+f"(d1), "+f"(d2), "+f"(d3)
        : "r"(a0), "r"(a1), "r"(a2), "r"(a3), "r"(b0), "r"(b1));
}
__device__ __forceinline__ uint32_t pack_bf16(float lo, float hi) {
    uint32_t r;
    asm("cvt.rn.bf16x2.f32 %0, %1, %2;" : "=r"(r) : "f"(hi), "f"(lo));
    return r;
}
__device__ __forceinline__ float ex2f(float x) {
    float r;
    asm("ex2.approx.f32 %0, %1;" : "=f"(r) : "f"(x));
    return r;
}
__device__ __forceinline__ float sigf(float z) {
    float e = ex2f(-1.4426950408889634f * z);
    float r;
    asm("rcp.approx.f32 %0, %1;" : "=f"(r) : "f"(1.f + e));
    return r;
}

__global__ __launch_bounds__(256, 4)
void seqatt_kernel(const float* __restrict__ queries,
                   const float* __restrict__ keys,
                   const int* __restrict__ keys_length,
                   const float* __restrict__ W1,
                   const float* __restrict__ b1,
                   const float* __restrict__ W2,
                   const float* __restrict__ b2,
                   const float* __restrict__ Wd,
                   float* __restrict__ out)
{
    extern __shared__ float sm[];
    bf16* K_s   = reinterpret_cast<bf16*>(sm + OFF_KS);
    bf16* H1_s  = reinterpret_cast<bf16*>(sm + OFF_H1);
    bf16* W_t   = reinterpret_cast<bf16*>(sm + OFF_WT);
    bf16* W2_t  = reinterpret_cast<bf16*>(sm + OFF_W2T);
    float* c_s  = sm + OFF_C;
    float* b2_s = sm + OFF_B2;
    float* Wd_s = sm + OFF_WD;
    float* q_s  = sm + OFF_Q;
    float* part = sm + OFF_PART;
    float* sc   = sm + OFF_SC;
    float* red  = sm + OFF_RED;
    float* red2 = sm + OFF_RED2;
    float* obuf = sm + OFF_OBUF;

    const int b   = blockIdx.x;
    const int tid = threadIdx.x;
    // keys_length is int32 on device (JAX x64-disabled downcasts int64->int32).
    int len = keys_length[b];
    len = len < 1 ? 1 : (len > T_DIM ? T_DIM : len);

    // ---- phase 0 ----
    if (tid < H_DIM) q_s[tid] = queries[b * H_DIM + tid];
    if (tid < D2) { b2_s[tid] = b2[tid]; Wd_s[tid] = Wd[tid]; }
    for (int i = tid; i < D1 * (D2 / 2); i += 256) {     // W2_t[n][j] = W2[j][n]
        int j = i / (D2 / 2), n2 = i - j * (D2 / 2);
        float2 v = *reinterpret_cast<const float2*>(W2 + j * D2 + 2 * n2);
        W2_t[(2 * n2)     * W2T_STR + j] = __float2bfloat16(v.x);
        W2_t[(2 * n2 + 1) * W2T_STR + j] = __float2bfloat16(v.y);
    }
    __syncthreads();

    for (int i = tid; i < H_DIM * (D1 / 2); i += 256) {  // W_t[j][h]
        int h = i / (D1 / 2), j2 = i - h * (D1 / 2);
        float2 wb = *reinterpret_cast<const float2*>(W1 + (64  + h) * D1 + 2 * j2);
        float2 wc = *reinterpret_cast<const float2*>(W1 + (128 + h) * D1 + 2 * j2);
        float2 wd = *reinterpret_cast<const float2*>(W1 + (192 + h) * D1 + 2 * j2);
        float qh = q_s[h];
        W_t[(2 * j2)     * WT_STR + h] = __float2bfloat16(wb.x - wc.x + qh * wd.x);
        W_t[(2 * j2 + 1) * WT_STR + h] = __float2bfloat16(wb.y - wc.y + qh * wd.y);
    }
    if (tid < 160) {   // c halves, summed in the layer-1 epilogue
        int seg = (tid >= 80) ? 1 : 0;
        int j = tid - 80 * seg;
        float acc = seg ? 0.f : b1[j];
        const float* p1 = W1 + (32 * seg) * D1 + j;
        const float* p2 = W1 + (128 + 32 * seg) * D1 + j;
        const float* qq = q_s + 32 * seg;
        #pragma unroll 8
        for (int h = 0; h < 32; h++)
            acc += qq[h] * (p1[h * D1] + p2[h * D1]);
        c_s[seg * 80 + j] = acc;
    }

    const int w    = tid >> 5;
    const int lane = tid & 31;
    const int gid  = lane >> 2;
    const int tig  = lane & 3;
    const int m    = w & 3;
    const int arow = 16 * m + gid;
    const int ntb0 = (w >> 2) * 5;
    const int ntO2 = (w >> 2) * 3;

    const int r8  = lane & 7;
    const int mi  = lane >> 3;
    const int mi2 = mi & 1;

    const uint32_t aA1 = cvsm(K_s)  + 2 * ((16 * m + r8 + ((mi & 1) << 3)) * K_STR  + ((mi >> 1) << 3));
    const uint32_t aA2 = cvsm(H1_s) + 2 * ((16 * m + r8 + ((mi & 1) << 3)) * H1_STR + ((mi >> 1) << 3));
    const uint32_t aB01 = cvsm(W_t) + 2 * ((8 * (ntb0 + (mi >> 1)) + r8) * WT_STR + ((mi & 1) << 3));
    const uint32_t aB23 = aB01 + 2 * (16 * WT_STR);
    const uint32_t aB4  = cvsm(W_t) + 2 * ((8 * (ntb0 + 4) + r8) * WT_STR + (mi2 << 3));
    const uint32_t aC01 = cvsm(W2_t) + 2 * ((8 * (ntO2 + (mi >> 1)) + r8) * W2T_STR + ((mi & 1) << 3));
    const uint32_t aC2  = cvsm(W2_t) + 2 * ((8 * (ntO2 + 2) + r8) * W2T_STR + (mi2 << 3));

    const float* Kbase = keys + (size_t)b * T_DIM * H_DIM;
    const int nchunk = (len + 63) >> 6;

    const int srow = tid >> 4;
    const int scol = (tid & 15) << 2;
    bf16* sdst0 = K_s + srow * K_STR + scol;
    const int phalf = (w >> 2) * 64;

    // ---- prologue: stage chunk 0 ----
    {
        const float* g0 = Kbase + srow * H_DIM + scol;
        #pragma unroll
        for (int it = 0; it < 4; it++) {
            float4 f = *reinterpret_cast<const float4*>(g0 + it * (16 * H_DIM));
            uint2 u;
            u.x = pack_bf16(f.x, f.y);
            u.y = pack_bf16(f.z, f.w);
            *reinterpret_cast<uint2*>(sdst0 + it * (16 * K_STR)) = u;
        }
    }

    for (int ch = 0; ch < nchunk; ch++) {
        // tail-tile skip: this warp's 16-row m-tile has no valid rows?
        // (uniform across the warp; skipped sections contain no barriers)
        const bool active = (16 * m) < (len - (ch << 6));

        __syncthreads();   // A: K_s (and at ch0, W_t/c) ready

        // ---- layer 1 ----
        if (active) {
            float acc1[5][4];
            #pragma unroll
            for (int nt = 0; nt < 5; nt++)
                #pragma unroll
                for (int i = 0; i < 4; i++) acc1[nt][i] = 0.f;

            #pragma unroll
            for (int ks = 0; ks < 4; ks++) {
                const uint32_t off = 32 * ks;
                uint32_t a0, a1, a2, a3;
                ldm_x4(a0, a1, a2, a3, aA1 + off);
                uint32_t b0, b1r, b2r, b3, b4, b5;
                ldm_x4(b0, b1r, b2r, b3, aB01 + off);
                mma16(acc1[0][0], acc1[0][1], acc1[0][2], acc1[0][3], a0, a1, a2, a3, b0, b1r);
                mma16(acc1[1][0], acc1[1][1], acc1[1][2], acc1[1][3], a0, a1, a2, a3, b2r, b3);
                ldm_x4(b0, b1r, b2r, b3, aB23 + off);
                mma16(acc1[2][0], acc1[2][1], acc1[2][2], acc1[2][3], a0, a1, a2, a3, b0, b1r);
                mma16(acc1[3][0], acc1[3][1], acc1[3][2], acc1[3][3], a0, a1, a2, a3, b2r, b3);
                ldm_x2(b4, b5, aB4 + off);
                mma16(acc1[4][0], acc1[4][1], acc1[4][2], acc1[4][3], a0, a1, a2, a3, b4, b5);
            }
            #pragma unroll
            for (int nt = 0; nt < 5; nt++) {
                int n0 = 8 * (ntb0 + nt) + 2 * tig;
                float2 cA = *reinterpret_cast<const float2*>(c_s + n0);
                float2 cB = *reinterpret_cast<const float2*>(c_s + 80 + n0);
                float ccx = cA.x + cB.x, ccy = cA.y + cB.y;
                uint32_t lo = pack_bf16(sigf(acc1[nt][0] + ccx), sigf(acc1[nt][1] + ccy));
                uint32_t hi = pack_bf16(sigf(acc1[nt][2] + ccx), sigf(acc1[nt][3] + ccy));
                *reinterpret_cast<uint32_t*>(H1_s + arow * H1_STR + n0) = lo;
                *reinterpret_cast<uint32_t*>(H1_s + (arow + 8) * H1_STR + n0) = hi;
            }
        }
        __syncthreads();   // B: H1 ready; all K_s reads done

        // ---- prefetch next K chunk into registers ----
        const bool has_next = (ch + 1) < nchunk;
        float4 pf0, pf1, pf2, pf3;
        if (has_next) {
            const int t0n = (ch + 1) << 6;
            if (t0n + 64 <= T_DIM) {
                const float* g0 = Kbase + (t0n + srow) * H_DIM + scol;
                pf0 = *reinterpret_cast<const float4*>(g0);
                pf1 = *reinterpret_cast<const float4*>(g0 + 16 * H_DIM);
                pf2 = *reinterpret_cast<const float4*>(g0 + 32 * H_DIM);
                pf3 = *reinterpret_cast<const float4*>(g0 + 48 * H_DIM);
            } else {
                int r0 = t0n + srow;
                int r1 = r0 + 16, r2 = r0 + 32, r3 = r0 + 48;
                r0 = r0 < T_DIM ? r0 : T_DIM - 1;
                r1 = r1 < T_DIM ? r1 : T_DIM - 1;
                r2 = r2 < T_DIM ? r2 : T_DIM - 1;
                r3 = r3 < T_DIM ? r3 : T_DIM - 1;
                pf0 = *reinterpret_cast<const float4*>(Kbase + r0 * H_DIM + scol);
                pf1 = *reinterpret_cast<const float4*>(Kbase + r1 * H_DIM + scol);
                pf2 = *reinterpret_cast<const float4*>(Kbase + r2 * H_DIM + scol);
                pf3 = *reinterpret_cast<const float4*>(Kbase + r3 * H_DIM + scol);
            }
        }

        // ---- layer 2 + head ----
        if (active) {
            float s0 = 0.f, s1 = 0.f;
            if (w < 4) {
                float acc2[3][4];
                #pragma unroll
                for (int nt = 0; nt < 3; nt++)
                    #pragma unroll
                    for (int i = 0; i < 4; i++) acc2[nt][i] = 0.f;
                #pragma unroll
                for (int ks = 0; ks < 5; ks++) {
                    const uint32_t off = 32 * ks;
                    uint32_t a0, a1, a2, a3, b0, b1r, b2r, b3;
                    ldm_x4(a0, a1, a2, a3, aA2 + off);
                    ldm_x4(b0, b1r, b2r, b3, aC01 + off);
                    mma16(acc2[0][0], acc2[0][1], acc2[0][2], acc2[0][3], a0, a1, a2, a3, b0, b1r);
                    mma16(acc2[1][0], acc2[1][1], acc2[1][2], acc2[1][3], a0, a1, a2, a3, b2r, b3);
                    ldm_x2(b0, b1r, aC2 + off);
                    mma16(acc2[2][0], acc2[2][1], acc2[2][2], acc2[2][3], a0, a1, a2, a3, b0, b1r);
                }
                #pragma unroll
                for (int nt = 0; nt < 3; nt++) {
                    int n0 = 8 * (ntO2 + nt) + 2 * tig;
                    float2 bb = *reinterpret_cast<const float2*>(b2_s + n0);
                    float2 wd = *reinterpret_cast<const float2*>(Wd_s + n0);
                    s0 += sigf(acc2[nt][0] + bb.x) * wd.x + sigf(acc2[nt][1] + bb.y) * wd.y;
                    s1 += sigf(acc2[nt][2] + bb.x) * wd.x + sigf(acc2[nt][3] + bb.y) * wd.y;
                }
            } else {
                float acc2[2][4];
                #pragma unroll
                for (int nt = 0; nt < 2; nt++)
                    #pragma unroll
                    for (int i = 0; i < 4; i++) acc2[nt][i] = 0.f;
                #pragma unroll
                for (int ks = 0; ks < 5; ks++) {
                    const uint32_t off = 32 * ks;
                    uint32_t a0, a1, a2, a3, b0, b1r, b2r, b3;
                    ldm_x4(a0, a1, a2, a3, aA2 + off);
                    ldm_x4(b0, b1r, b2r, b3, aC01 + off);
                    mma16(acc2[0][0], acc2[0][1], acc2[0][2], acc2[0][3], a0, a1, a2, a3, b0, b1r);
                    mma16(acc2[1][0], acc2[1][1], acc2[1][2], acc2[1][3], a0, a1, a2, a3, b2r, b3);
                }
                #pragma unroll
                for (int nt = 0; nt < 2; nt++) {
                    int n0 = 8 * (ntO2 + nt) + 2 * tig;
                    float2 bb = *reinterpret_cast<const float2*>(b2_s + n0);
                    float2 wd = *reinterpret_cast<const float2*>(Wd_s + n0);
                    s0 += sigf(acc2[nt][0] + bb.x) * wd.x + sigf(acc2[nt][1] + bb.y) * wd.y;
                    s1 += sigf(acc2[nt][2] + bb.x) * wd.x + sigf(acc2[nt][3] + bb.y) * wd.y;
                }
            }
            #pragma unroll
            for (int off = 1; off < 4; off <<= 1) {
                s0 += __shfl_xor_sync(0xffffffffu, s0, off);
                s1 += __shfl_xor_sync(0xffffffffu, s1, off);
            }
            if (tig == 0) {
                float* p = part + ch * 128 + phalf + 16 * m + gid;
                p[0] = s0;
                p[8] = s1;
            }
        }

        if (has_next) {
            uint2 u;
            u.x = pack_bf16(pf0.x, pf0.y); u.y = pack_bf16(pf0.z, pf0.w);
            *reinterpret_cast<uint2*>(sdst0) = u;
            u.x = pack_bf16(pf1.x, pf1.y); u.y = pack_bf16(pf1.z, pf1.w);
            *reinterpret_cast<uint2*>(sdst0 + 16 * K_STR) = u;
            u.x = pack_bf16(pf2.x, pf2.y); u.y = pack_bf16(pf2.z, pf2.w);
            *reinterpret_cast<uint2*>(sdst0 + 32 * K_STR) = u;
            u.x = pack_bf16(pf3.x, pf3.y); u.y = pack_bf16(pf3.z, pf3.w);
            *reinterpret_cast<uint2*>(sdst0 + 48 * K_STR) = u;
        }
    }
    __syncthreads();   // part[] visible

    // ---- softmax (2 barriers): scale 1/sqrt(64); bd cancels ----
    float v = -INFINITY;
    if (tid < len) {
        const float* p = part + (tid >> 6) * 128 + (tid & 63);
        v = (p[0] + p[64]) * 0.125f;
    }
    float mx = v;
    #pragma unroll
    for (int s = 16; s; s >>= 1) mx = fmaxf(mx, __shfl_xor_sync(0xffffffffu, mx, s));
    if (lane == 0) red[w] = mx;
    __syncthreads();
    float M = red[0];
    #pragma unroll
    for (int i = 1; i < 8; i++) M = fmaxf(M, red[i]);

    float e = (tid < len) ? ex2f(1.4426950408889634f * (v - M)) : 0.f;
    if (tid < T_DIM) sc[tid] = e;       // unnormalized
    float s = e;
    #pragma unroll
    for (int o = 16; o; o >>= 1) s += __shfl_xor_sync(0xffffffffu, s, o);
    if (lane == 0) red2[w] = s;
    __syncthreads();                     // sc[] + red2[] visible
    float ssum = red2[0];
    #pragma unroll
    for (int i = 1; i < 8; i++) ssum += red2[i];
    const float inv_sum = 1.f / ssum;

    // ---- out[h] = inv_sum * sum_t e[t]*keys[b,t,h]; float4, 16 t-groups ----
    {
        const int g  = tid >> 4;            // 0..15 t-group
        const int c4 = (tid & 15) << 2;     // h base
        const float* pk = Kbase + g * H_DIM + c4;
        float4 acc = make_float4(0.f, 0.f, 0.f, 0.f);
        for (int t = g; t < len; t += 16) {
            float wt = sc[t];
            float4 k4 = *reinterpret_cast<const float4*>(pk);
            acc.x += wt * k4.x; acc.y += wt * k4.y;
            acc.z += wt * k4.z; acc.w += wt * k4.w;
            pk += 16 * H_DIM;
        }
        *reinterpret_cast<float4*>(obuf + g * 64 + c4) = acc;
        __syncthreads();
        if (tid < H_DIM) {
            float o = 0.f;
            #pragma unroll
            for (int i = 0; i < 16; i++) o += obuf[i * 64 + tid];
            out[b * H_DIM + tid] = inv_sum * o;
        }
    }
}

extern "C" void kernel_launch(void* const* d_in, const int* in_sizes, int n_in,
                              void* d_out, int out_size)
{
    const float* queries = (const float*)d_in[0];
    const float* keys    = (const float*)d_in[1];
    const int*   klen    = (const int*)d_in[2];
    const float* W1      = (const float*)d_in[3];
    const float* b1      = (const float*)d_in[4];
    const float* W2      = (const float*)d_in[5];
    const float* b2      = (const float*)d_in[6];
    const float* Wd      = (const float*)d_in[7];
    // d_in[8] = bd : uniform shift, cancels in softmax
    float* out = (float*)d_out;

    const int B = in_sizes[2];  // keys_length count
    const size_t smem = SMEM_FLOATS * sizeof(float);
    cudaFuncSetAttribute(seqatt_kernel,
                         cudaFuncAttributeMaxDynamicSharedMemorySize, (int)smem);
    seqatt_kernel<<<B, 256, smem>>>(queries, keys, klen, W1, b1, W2, b2, Wd, out);
}